// round 5
// baseline (speedup 1.0000x reference)
#include <cuda_runtime.h>
#include <cuda_bf16.h>
#include <math.h>

// ---------------------------------------------------------------------------
// Scratch (allocation-free: __device__ globals)
// ---------------------------------------------------------------------------
#define MAXN 4096
__device__ float g_h1[MAXN * 32 * 14 * 14];   // conv1+pool output (N,32,14,14)
__device__ float g_h2[MAXN * 3136];           // conv2+pool output (N,64,7,7) flattened
__device__ float g_fc[MAXN * 32];             // FC output (N,32)

// ---------------------------------------------------------------------------
// f32x2 packed helpers (Blackwell)
// ---------------------------------------------------------------------------
typedef unsigned long long u64;

__device__ __forceinline__ u64 pack2(float lo, float hi) {
    u64 r;
    asm("mov.b64 %0, {%1, %2};" : "=l"(r) : "f"(lo), "f"(hi));
    return r;
}
__device__ __forceinline__ void unpack2(u64 v, float& lo, float& hi) {
    asm("mov.b64 {%0, %1}, %2;" : "=f"(lo), "=f"(hi) : "l"(v));
}
__device__ __forceinline__ u64 dup2(float v) { return pack2(v, v); }
__device__ __forceinline__ u64 fma2(u64 a, u64 b, u64 c) {
    u64 r;
    asm("fma.rn.f32x2 %0, %1, %2, %3;" : "=l"(r) : "l"(a), "l"(b), "l"(c));
    return r;
}

// ---------------------------------------------------------------------------
// Kernel 1: conv1 (1->32, 3x3, pad 1) + relu + maxpool2   (28x28 -> 14x14)
// One block per image. 256 threads.
// ---------------------------------------------------------------------------
__global__ __launch_bounds__(256)
void conv1_kernel(const float* __restrict__ x,
                  const float* __restrict__ w,      // (32,1,3,3)
                  const float* __restrict__ bias)   // (32,)
{
    __shared__ __align__(16) float s_in[30 * 30];   // padded input
    __shared__ __align__(16) float s_w[9 * 32];     // [k][co]
    __shared__ float s_b[32];

    const int n   = blockIdx.x;
    const int tid = threadIdx.x;

    // zero padded input + load weights transposed
    for (int i = tid; i < 900; i += 256) s_in[i] = 0.0f;
    for (int i = tid; i < 288; i += 256) {          // FIX: was `if (tid < 288)`
        int co = i / 9, k = i % 9;
        s_w[k * 32 + co] = w[co * 9 + k];
    }
    if (tid < 32) s_b[tid] = bias[tid];
    __syncthreads();

    const float* xb = x + n * 784;
    for (int i = tid; i < 784; i += 256) {
        int y = i / 28, c = i % 28;
        s_in[(y + 1) * 30 + (c + 1)] = xb[i];
    }
    __syncthreads();

    const float2* s_w2 = reinterpret_cast<const float2*>(s_w);
    float* outb = g_h1 + n * 6272;

    // items: 196 pooled positions x 16 channel-pairs
    for (int it = tid; it < 3136; it += 256) {
        const int pair = it & 15;
        const int pos  = it >> 4;           // 0..195
        const int py   = pos / 14;
        const int px   = pos - py * 14;
        const int co0  = pair * 2;

        // 4x4 input patch (padded coords rows 2py..2py+3, cols 2px..2px+3)
        float pv[4][4];
#pragma unroll
        for (int r = 0; r < 4; r++)
#pragma unroll
            for (int c = 0; c < 4; c++)
                pv[r][c] = s_in[(2 * py + r) * 30 + (2 * px + c)];

        u64 binit = pack2(s_b[co0], s_b[co0 + 1]);
        u64 acc[4] = {binit, binit, binit, binit};

#pragma unroll
        for (int ky = 0; ky < 3; ky++)
#pragma unroll
            for (int kx = 0; kx < 3; kx++) {
                float2 wf = s_w2[(ky * 3 + kx) * 16 + pair];
                u64 wv = pack2(wf.x, wf.y);
#pragma unroll
                for (int dy = 0; dy < 2; dy++)
#pragma unroll
                    for (int dx = 0; dx < 2; dx++)
                        acc[dy * 2 + dx] =
                            fma2(dup2(pv[dy + ky][dx + kx]), wv, acc[dy * 2 + dx]);
            }

        float l0, h0, l1, h1, l2, h2, l3, h3;
        unpack2(acc[0], l0, h0); unpack2(acc[1], l1, h1);
        unpack2(acc[2], l2, h2); unpack2(acc[3], l3, h3);
        float mlo = fmaxf(fmaxf(l0, l1), fmaxf(l2, l3));
        float mhi = fmaxf(fmaxf(h0, h1), fmaxf(h2, h3));
        mlo = fmaxf(mlo, 0.0f);
        mhi = fmaxf(mhi, 0.0f);
        outb[co0 * 196 + pos]       = mlo;
        outb[(co0 + 1) * 196 + pos] = mhi;
    }
}

// ---------------------------------------------------------------------------
// Kernel 2: conv2 (32->64, 3x3, pad 1) + relu + maxpool2   (14x14 -> 7x7)
// One block per image. 224 threads (7 warps: warp = pooled row, lane = co-pair).
// Dynamic smem: padded input 32x16x16 (32KB) + weights [ci][k][co] (72KB) + bias
// ---------------------------------------------------------------------------
#define C2_SMEM_FLOATS (8192 + 18432 + 64)
#define C2_SMEM_BYTES  (C2_SMEM_FLOATS * 4)

__global__ __launch_bounds__(224, 2)
void conv2_kernel(const float* __restrict__ w,      // (64,32,3,3)
                  const float* __restrict__ bias)   // (64,)
{
    extern __shared__ __align__(16) float smem[];
    float* s_in = smem;                 // [ci][16][16] padded, 8192 floats
    float* s_w  = smem + 8192;          // [(ci*9+k)*64 + co], 18432 floats
    float* s_b  = smem + 8192 + 18432;  // 64 floats

    const int n   = blockIdx.x;
    const int tid = threadIdx.x;
    const int nt  = blockDim.x;

    for (int i = tid; i < 8192; i += nt) s_in[i] = 0.0f;
    __syncthreads();

    const float* inb = g_h1 + n * 6272;
    for (int i = tid; i < 6272; i += nt) {
        int ci = i / 196, rem = i - ci * 196;
        int y = rem / 14, xx = rem - y * 14;
        s_in[ci * 256 + (y + 1) * 16 + (xx + 1)] = inb[i];
    }
    for (int i = tid; i < 18432; i += nt) {
        int co = i / 288, rem = i - co * 288;   // rem = ci*9+k
        s_w[rem * 64 + co] = w[i];
    }
    for (int i = tid; i < 64; i += nt) s_b[i] = bias[i];
    __syncthreads();

    const int pair = tid & 31;          // co pair 0..31
    const int py   = tid >> 5;          // pooled row 0..6
    const int co0  = pair * 2;

    u64 binit = pack2(s_b[co0], s_b[co0 + 1]);
    u64 acc[7][4];
#pragma unroll
    for (int px = 0; px < 7; px++)
#pragma unroll
        for (int q = 0; q < 4; q++) acc[px][q] = binit;

#pragma unroll 1
    for (int ci = 0; ci < 32; ci++) {
        // load 4 padded rows (2py..2py+3), 16 cols each, via float4
        float rows[4][16];
#pragma unroll
        for (int rr = 0; rr < 4; rr++) {
            const float4* p =
                reinterpret_cast<const float4*>(s_in + ci * 256 + (2 * py + rr) * 16);
#pragma unroll
            for (int q = 0; q < 4; q++) {
                float4 v = p[q];
                rows[rr][4 * q + 0] = v.x;
                rows[rr][4 * q + 1] = v.y;
                rows[rr][4 * q + 2] = v.z;
                rows[rr][4 * q + 3] = v.w;
            }
        }

        const float* wbase = s_w + ci * 9 * 64 + co0;
#pragma unroll
        for (int ky = 0; ky < 3; ky++)
#pragma unroll
            for (int kx = 0; kx < 3; kx++) {
                u64 wv = *reinterpret_cast<const u64*>(wbase + (ky * 3 + kx) * 64);
#pragma unroll
                for (int px = 0; px < 7; px++)
#pragma unroll
                    for (int dy = 0; dy < 2; dy++)
#pragma unroll
                        for (int dx = 0; dx < 2; dx++)
                            acc[px][dy * 2 + dx] = fma2(
                                dup2(rows[dy + ky][2 * px + dx + kx]), wv,
                                acc[px][dy * 2 + dx]);
            }
    }

    float* outb = g_h2 + n * 3136;
#pragma unroll
    for (int px = 0; px < 7; px++) {
        float l0, h0, l1, h1, l2, h2, l3, h3;
        unpack2(acc[px][0], l0, h0); unpack2(acc[px][1], l1, h1);
        unpack2(acc[px][2], l2, h2); unpack2(acc[px][3], l3, h3);
        float mlo = fmaxf(fmaxf(fmaxf(l0, l1), fmaxf(l2, l3)), 0.0f);
        float mhi = fmaxf(fmaxf(fmaxf(h0, h1), fmaxf(h2, h3)), 0.0f);
        outb[co0 * 49 + py * 7 + px]       = mlo;
        outb[(co0 + 1) * 49 + py * 7 + px] = mhi;
    }
}

// ---------------------------------------------------------------------------
// Kernel 3: FC  (N,3136) @ (32,3136)^T + bias -> (N,32)
// Block = 32 images x 32 outputs; 256 threads, thread = (d, 4 images)
// ---------------------------------------------------------------------------
#define FC_KT 112   // 3136 = 28 * 112

__global__ __launch_bounds__(256)
void fc_kernel(const float* __restrict__ w,      // (32,3136)
               const float* __restrict__ bias)   // (32,)
{
    __shared__ __align__(16) float a_s[32 * FC_KT];      // [n][kk]
    __shared__ float b_s[FC_KT * 33];                    // [kk][d], padded

    const int tid = threadIdx.x;
    const int n0  = blockIdx.x * 32;
    const int d   = tid & 31;
    const int tr  = tid >> 5;   // 0..7

    float acc[4];
    float bv = bias[d];
#pragma unroll
    for (int i = 0; i < 4; i++) acc[i] = bv;

    for (int kt = 0; kt < 3136; kt += FC_KT) {
        __syncthreads();
        for (int i = tid; i < 32 * FC_KT; i += 256) {
            int r = i / FC_KT, c = i - r * FC_KT;
            a_s[r * FC_KT + c] = g_h2[(n0 + r) * 3136 + kt + c];
        }
        for (int i = tid; i < 32 * FC_KT; i += 256) {
            int r = i / FC_KT, c = i - r * FC_KT;
            b_s[c * 33 + r] = w[r * 3136 + kt + c];
        }
        __syncthreads();

#pragma unroll 4
        for (int kk = 0; kk < FC_KT; kk += 4) {
            float w0 = b_s[(kk + 0) * 33 + d];
            float w1 = b_s[(kk + 1) * 33 + d];
            float w2 = b_s[(kk + 2) * 33 + d];
            float w3 = b_s[(kk + 3) * 33 + d];
#pragma unroll
            for (int i = 0; i < 4; i++) {
                float4 av = *reinterpret_cast<const float4*>(
                    a_s + (tr * 4 + i) * FC_KT + kk);
                acc[i] = fmaf(av.x, w0, acc[i]);
                acc[i] = fmaf(av.y, w1, acc[i]);
                acc[i] = fmaf(av.z, w2, acc[i]);
                acc[i] = fmaf(av.w, w3, acc[i]);
            }
        }
    }

#pragma unroll
    for (int i = 0; i < 4; i++)
        g_fc[(n0 + tr * 4 + i) * 32 + d] = acc[i];
}

// ---------------------------------------------------------------------------
// Kernel 4: hyperbolic MLR  (N,32) -> (N,10), c = 1
// ---------------------------------------------------------------------------
__global__ __launch_bounds__(256)
void mlr_kernel(const float* __restrict__ hw,   // (10,32)
                const float* __restrict__ hb,   // (10,32)
                float* __restrict__ out, int total)
{
    int i = blockIdx.x * blockDim.x + threadIdx.x;
    if (i >= total) return;
    int n = i / 10;
    int k = i - n * 10;

    const float* xv = g_fc + n * 32;
    const float* wv = hw + k * 32;
    const float* bv = hb + k * 32;

    float x2 = 0.f, b2 = 0.f, w2 = 0.f, xb = 0.f, xw = 0.f, wb = 0.f;
#pragma unroll
    for (int j = 0; j < 32; j++) {
        float xj = xv[j], wj = wv[j], bj = bv[j];
        x2 += xj * xj;  b2 += bj * bj;  w2 += wj * wj;
        xb += xj * bj;  xw += xj * wj;  wb += wj * bj;
    }

    const float EPSf = 1e-5f;
    const float MN   = 0.99999f;                 // (1 - 1e-5)/sqrt(c), c=1

    float inner  = -xb;                          // x @ (-b)
    float w_norm = sqrtf(w2);
    float inv_wn = 1.0f / fmaxf(w_norm, 1e-12f);
    float wb_n   = -wb * inv_wn;                 // dot(wn, -b)
    float xw_n   = xw * inv_wn;                  // x @ wn

    float a_num = 1.0f + 2.0f * inner + x2;
    float b_num = 1.0f - b2;
    float denom = 1.0f + 2.0f * inner + x2 * b2;
    float alpha = a_num / fmaxf(denom, EPSf);
    float beta  = b_num / denom;                 // raw denom, as in source
    float mob2  = alpha * alpha * b2 + 2.0f * alpha * beta * inner
                + beta * beta * x2;
    float sq    = sqrtf(mob2);
    float normalizer = (sq > MN) ? (MN / fmaxf(sq, EPSf)) : 1.0f;
    float mob2f = (sq < MN) ? mob2 : (MN * MN);
    float hyp   = (alpha * wb_n + beta * xw_n) * normalizer;
    float asin_in = 2.0f * hyp / fmaxf(1.0f - mob2f, EPSf);

    out[i] = (2.0f / fmaxf(1.0f - b2, EPSf)) * w_norm * asinhf(asin_in);
}

// ---------------------------------------------------------------------------
// Launch
// Inputs (metadata order): x, conv1_w, conv1_b, conv2_w, conv2_b,
//                          fc_w, fc_b, hyp_w, hyp_b
// ---------------------------------------------------------------------------
extern "C" void kernel_launch(void* const* d_in, const int* in_sizes, int n_in,
                              void* d_out, int out_size) {
    const float* x   = (const float*)d_in[0];
    const float* w1  = (const float*)d_in[1];
    const float* b1  = (const float*)d_in[2];
    const float* w2  = (const float*)d_in[3];
    const float* b2  = (const float*)d_in[4];
    const float* fw  = (const float*)d_in[5];
    const float* fb  = (const float*)d_in[6];
    const float* hw  = (const float*)d_in[7];
    const float* hb  = (const float*)d_in[8];
    float* out = (float*)d_out;

    const int N = in_sizes[0] / 784;

    cudaFuncSetAttribute(conv2_kernel,
                         cudaFuncAttributeMaxDynamicSharedMemorySize,
                         C2_SMEM_BYTES);

    conv1_kernel<<<N, 256>>>(x, w1, b1);
    conv2_kernel<<<N, 224, C2_SMEM_BYTES>>>(w2, b2);
    fc_kernel<<<N / 32, 256>>>(fw, fb);
    int total = N * 10;
    mlr_kernel<<<(total + 255) / 256, 256>>>(hw, hb, out, total);
}

// round 6
// speedup vs baseline: 1.0058x; 1.0058x over previous
#include <cuda_runtime.h>
#include <cuda_bf16.h>
#include <math.h>

// ---------------------------------------------------------------------------
// Scratch (allocation-free: __device__ globals)
// ---------------------------------------------------------------------------
#define MAXN 4096
__device__ float g_h1[MAXN * 32 * 14 * 14];   // conv1+pool output (N,32,14,14)
__device__ float g_h2[MAXN * 3136];           // conv2+pool output (N,64,7,7) flattened
__device__ float g_fc[MAXN * 32];             // FC output (N,32)

// ---------------------------------------------------------------------------
// f32x2 packed helpers (Blackwell)
// ---------------------------------------------------------------------------
typedef unsigned long long u64;

__device__ __forceinline__ u64 pack2(float lo, float hi) {
    u64 r;
    asm("mov.b64 %0, {%1, %2};" : "=l"(r) : "f"(lo), "f"(hi));
    return r;
}
__device__ __forceinline__ void unpack2(u64 v, float& lo, float& hi) {
    asm("mov.b64 {%0, %1}, %2;" : "=f"(lo), "=f"(hi) : "l"(v));
}
__device__ __forceinline__ u64 dup2(float v) { return pack2(v, v); }
__device__ __forceinline__ u64 fma2(u64 a, u64 b, u64 c) {
    u64 r;
    asm("fma.rn.f32x2 %0, %1, %2, %3;" : "=l"(r) : "l"(a), "l"(b), "l"(c));
    return r;
}

// ---------------------------------------------------------------------------
// Kernel 1: conv1 (1->32, 3x3, pad 1) + relu + maxpool2   (28x28 -> 14x14)
// One block per image. 256 threads.
// ---------------------------------------------------------------------------
__global__ __launch_bounds__(256)
void conv1_kernel(const float* __restrict__ x,
                  const float* __restrict__ w,      // (32,1,3,3)
                  const float* __restrict__ bias)   // (32,)
{
    __shared__ __align__(16) float s_in[30 * 30];   // padded input
    __shared__ __align__(16) float s_w[9 * 32];     // [k][co]
    __shared__ float s_b[32];

    const int n   = blockIdx.x;
    const int tid = threadIdx.x;

    // zero padded input + load weights transposed
    for (int i = tid; i < 900; i += 256) s_in[i] = 0.0f;
    for (int i = tid; i < 288; i += 256) {          // FIX: was `if (tid < 288)`
        int co = i / 9, k = i % 9;
        s_w[k * 32 + co] = w[co * 9 + k];
    }
    if (tid < 32) s_b[tid] = bias[tid];
    __syncthreads();

    const float* xb = x + n * 784;
    for (int i = tid; i < 784; i += 256) {
        int y = i / 28, c = i % 28;
        s_in[(y + 1) * 30 + (c + 1)] = xb[i];
    }
    __syncthreads();

    const float2* s_w2 = reinterpret_cast<const float2*>(s_w);
    float* outb = g_h1 + n * 6272;

    // items: 196 pooled positions x 16 channel-pairs
    for (int it = tid; it < 3136; it += 256) {
        const int pair = it & 15;
        const int pos  = it >> 4;           // 0..195
        const int py   = pos / 14;
        const int px   = pos - py * 14;
        const int co0  = pair * 2;

        // 4x4 input patch (padded coords rows 2py..2py+3, cols 2px..2px+3)
        float pv[4][4];
#pragma unroll
        for (int r = 0; r < 4; r++)
#pragma unroll
            for (int c = 0; c < 4; c++)
                pv[r][c] = s_in[(2 * py + r) * 30 + (2 * px + c)];

        u64 binit = pack2(s_b[co0], s_b[co0 + 1]);
        u64 acc[4] = {binit, binit, binit, binit};

#pragma unroll
        for (int ky = 0; ky < 3; ky++)
#pragma unroll
            for (int kx = 0; kx < 3; kx++) {
                float2 wf = s_w2[(ky * 3 + kx) * 16 + pair];
                u64 wv = pack2(wf.x, wf.y);
#pragma unroll
                for (int dy = 0; dy < 2; dy++)
#pragma unroll
                    for (int dx = 0; dx < 2; dx++)
                        acc[dy * 2 + dx] =
                            fma2(dup2(pv[dy + ky][dx + kx]), wv, acc[dy * 2 + dx]);
            }

        float l0, h0, l1, h1, l2, h2, l3, h3;
        unpack2(acc[0], l0, h0); unpack2(acc[1], l1, h1);
        unpack2(acc[2], l2, h2); unpack2(acc[3], l3, h3);
        float mlo = fmaxf(fmaxf(l0, l1), fmaxf(l2, l3));
        float mhi = fmaxf(fmaxf(h0, h1), fmaxf(h2, h3));
        mlo = fmaxf(mlo, 0.0f);
        mhi = fmaxf(mhi, 0.0f);
        outb[co0 * 196 + pos]       = mlo;
        outb[(co0 + 1) * 196 + pos] = mhi;
    }
}

// ---------------------------------------------------------------------------
// Kernel 2: conv2 (32->64, 3x3, pad 1) + relu + maxpool2   (14x14 -> 7x7)
// One block per image. 224 threads (7 warps: warp = pooled row, lane = co-pair).
// Dynamic smem: padded input 32x16x16 (32KB) + weights [ci][k][co] (72KB) + bias
// ---------------------------------------------------------------------------
#define C2_SMEM_FLOATS (8192 + 18432 + 64)
#define C2_SMEM_BYTES  (C2_SMEM_FLOATS * 4)

__global__ __launch_bounds__(224, 2)
void conv2_kernel(const float* __restrict__ w,      // (64,32,3,3)
                  const float* __restrict__ bias)   // (64,)
{
    extern __shared__ __align__(16) float smem[];
    float* s_in = smem;                 // [ci][16][16] padded, 8192 floats
    float* s_w  = smem + 8192;          // [(ci*9+k)*64 + co], 18432 floats
    float* s_b  = smem + 8192 + 18432;  // 64 floats

    const int n   = blockIdx.x;
    const int tid = threadIdx.x;
    const int nt  = blockDim.x;

    for (int i = tid; i < 8192; i += nt) s_in[i] = 0.0f;
    __syncthreads();

    const float* inb = g_h1 + n * 6272;
    for (int i = tid; i < 6272; i += nt) {
        int ci = i / 196, rem = i - ci * 196;
        int y = rem / 14, xx = rem - y * 14;
        s_in[ci * 256 + (y + 1) * 16 + (xx + 1)] = inb[i];
    }
    for (int i = tid; i < 18432; i += nt) {
        int co = i / 288, rem = i - co * 288;   // rem = ci*9+k
        s_w[rem * 64 + co] = w[i];
    }
    for (int i = tid; i < 64; i += nt) s_b[i] = bias[i];
    __syncthreads();

    const int pair = tid & 31;          // co pair 0..31
    const int py   = tid >> 5;          // pooled row 0..6
    const int co0  = pair * 2;

    u64 binit = pack2(s_b[co0], s_b[co0 + 1]);
    u64 acc[7][4];
#pragma unroll
    for (int px = 0; px < 7; px++)
#pragma unroll
        for (int q = 0; q < 4; q++) acc[px][q] = binit;

#pragma unroll 1
    for (int ci = 0; ci < 32; ci++) {
        // load 4 padded rows (2py..2py+3), 16 cols each, via float4
        float rows[4][16];
#pragma unroll
        for (int rr = 0; rr < 4; rr++) {
            const float4* p =
                reinterpret_cast<const float4*>(s_in + ci * 256 + (2 * py + rr) * 16);
#pragma unroll
            for (int q = 0; q < 4; q++) {
                float4 v = p[q];
                rows[rr][4 * q + 0] = v.x;
                rows[rr][4 * q + 1] = v.y;
                rows[rr][4 * q + 2] = v.z;
                rows[rr][4 * q + 3] = v.w;
            }
        }

        const float* wbase = s_w + ci * 9 * 64 + co0;
#pragma unroll
        for (int ky = 0; ky < 3; ky++)
#pragma unroll
            for (int kx = 0; kx < 3; kx++) {
                u64 wv = *reinterpret_cast<const u64*>(wbase + (ky * 3 + kx) * 64);
#pragma unroll
                for (int px = 0; px < 7; px++)
#pragma unroll
                    for (int dy = 0; dy < 2; dy++)
#pragma unroll
                        for (int dx = 0; dx < 2; dx++)
                            acc[px][dy * 2 + dx] = fma2(
                                dup2(rows[dy + ky][2 * px + dx + kx]), wv,
                                acc[px][dy * 2 + dx]);
            }
    }

    float* outb = g_h2 + n * 3136;
#pragma unroll
    for (int px = 0; px < 7; px++) {
        float l0, h0, l1, h1, l2, h2, l3, h3;
        unpack2(acc[px][0], l0, h0); unpack2(acc[px][1], l1, h1);
        unpack2(acc[px][2], l2, h2); unpack2(acc[px][3], l3, h3);
        float mlo = fmaxf(fmaxf(fmaxf(l0, l1), fmaxf(l2, l3)), 0.0f);
        float mhi = fmaxf(fmaxf(fmaxf(h0, h1), fmaxf(h2, h3)), 0.0f);
        outb[co0 * 49 + py * 7 + px]       = mlo;
        outb[(co0 + 1) * 49 + py * 7 + px] = mhi;
    }
}

// ---------------------------------------------------------------------------
// Kernel 3: FC  (N,3136) @ (32,3136)^T + bias -> (N,32)
// Block = 32 images x 32 outputs; 256 threads, thread = (d, 4 images)
// ---------------------------------------------------------------------------
#define FC_KT 112   // 3136 = 28 * 112

__global__ __launch_bounds__(256)
void fc_kernel(const float* __restrict__ w,      // (32,3136)
               const float* __restrict__ bias)   // (32,)
{
    __shared__ __align__(16) float a_s[32 * FC_KT];      // [n][kk]
    __shared__ float b_s[FC_KT * 33];                    // [kk][d], padded

    const int tid = threadIdx.x;
    const int n0  = blockIdx.x * 32;
    const int d   = tid & 31;
    const int tr  = tid >> 5;   // 0..7

    float acc[4];
    float bv = bias[d];
#pragma unroll
    for (int i = 0; i < 4; i++) acc[i] = bv;

    for (int kt = 0; kt < 3136; kt += FC_KT) {
        __syncthreads();
        for (int i = tid; i < 32 * FC_KT; i += 256) {
            int r = i / FC_KT, c = i - r * FC_KT;
            a_s[r * FC_KT + c] = g_h2[(n0 + r) * 3136 + kt + c];
        }
        for (int i = tid; i < 32 * FC_KT; i += 256) {
            int r = i / FC_KT, c = i - r * FC_KT;
            b_s[c * 33 + r] = w[r * 3136 + kt + c];
        }
        __syncthreads();

#pragma unroll 4
        for (int kk = 0; kk < FC_KT; kk += 4) {
            float w0 = b_s[(kk + 0) * 33 + d];
            float w1 = b_s[(kk + 1) * 33 + d];
            float w2 = b_s[(kk + 2) * 33 + d];
            float w3 = b_s[(kk + 3) * 33 + d];
#pragma unroll
            for (int i = 0; i < 4; i++) {
                float4 av = *reinterpret_cast<const float4*>(
                    a_s + (tr * 4 + i) * FC_KT + kk);
                acc[i] = fmaf(av.x, w0, acc[i]);
                acc[i] = fmaf(av.y, w1, acc[i]);
                acc[i] = fmaf(av.z, w2, acc[i]);
                acc[i] = fmaf(av.w, w3, acc[i]);
            }
        }
    }

#pragma unroll
    for (int i = 0; i < 4; i++)
        g_fc[(n0 + tr * 4 + i) * 32 + d] = acc[i];
}

// ---------------------------------------------------------------------------
// Kernel 4: hyperbolic MLR  (N,32) -> (N,10), c = 1
// ---------------------------------------------------------------------------
__global__ __launch_bounds__(256)
void mlr_kernel(const float* __restrict__ hw,   // (10,32)
                const float* __restrict__ hb,   // (10,32)
                float* __restrict__ out, int total)
{
    int i = blockIdx.x * blockDim.x + threadIdx.x;
    if (i >= total) return;
    int n = i / 10;
    int k = i - n * 10;

    const float* xv = g_fc + n * 32;
    const float* wv = hw + k * 32;
    const float* bv = hb + k * 32;

    float x2 = 0.f, b2 = 0.f, w2 = 0.f, xb = 0.f, xw = 0.f, wb = 0.f;
#pragma unroll
    for (int j = 0; j < 32; j++) {
        float xj = xv[j], wj = wv[j], bj = bv[j];
        x2 += xj * xj;  b2 += bj * bj;  w2 += wj * wj;
        xb += xj * bj;  xw += xj * wj;  wb += wj * bj;
    }

    const float EPSf = 1e-5f;
    const float MN   = 0.99999f;                 // (1 - 1e-5)/sqrt(c), c=1

    float inner  = -xb;                          // x @ (-b)
    float w_norm = sqrtf(w2);
    float inv_wn = 1.0f / fmaxf(w_norm, 1e-12f);
    float wb_n   = -wb * inv_wn;                 // dot(wn, -b)
    float xw_n   = xw * inv_wn;                  // x @ wn

    float a_num = 1.0f + 2.0f * inner + x2;
    float b_num = 1.0f - b2;
    float denom = 1.0f + 2.0f * inner + x2 * b2;
    float alpha = a_num / fmaxf(denom, EPSf);
    float beta  = b_num / denom;                 // raw denom, as in source
    float mob2  = alpha * alpha * b2 + 2.0f * alpha * beta * inner
                + beta * beta * x2;
    float sq    = sqrtf(mob2);
    float normalizer = (sq > MN) ? (MN / fmaxf(sq, EPSf)) : 1.0f;
    float mob2f = (sq < MN) ? mob2 : (MN * MN);
    float hyp   = (alpha * wb_n + beta * xw_n) * normalizer;
    float asin_in = 2.0f * hyp / fmaxf(1.0f - mob2f, EPSf);

    out[i] = (2.0f / fmaxf(1.0f - b2, EPSf)) * w_norm * asinhf(asin_in);
}

// ---------------------------------------------------------------------------
// Launch
// Inputs (metadata order): x, conv1_w, conv1_b, conv2_w, conv2_b,
//                          fc_w, fc_b, hyp_w, hyp_b
// ---------------------------------------------------------------------------
extern "C" void kernel_launch(void* const* d_in, const int* in_sizes, int n_in,
                              void* d_out, int out_size) {
    const float* x   = (const float*)d_in[0];
    const float* w1  = (const float*)d_in[1];
    const float* b1  = (const float*)d_in[2];
    const float* w2  = (const float*)d_in[3];
    const float* b2  = (const float*)d_in[4];
    const float* fw  = (const float*)d_in[5];
    const float* fb  = (const float*)d_in[6];
    const float* hw  = (const float*)d_in[7];
    const float* hb  = (const float*)d_in[8];
    float* out = (float*)d_out;

    const int N = in_sizes[0] / 784;

    cudaFuncSetAttribute(conv2_kernel,
                         cudaFuncAttributeMaxDynamicSharedMemorySize,
                         C2_SMEM_BYTES);

    conv1_kernel<<<N, 256>>>(x, w1, b1);
    conv2_kernel<<<N, 224, C2_SMEM_BYTES>>>(w2, b2);
    fc_kernel<<<N / 32, 256>>>(fw, fb);
    int total = N * 10;
    mlr_kernel<<<(total + 255) / 256, 256>>>(hw, hb, out, total);
}

// round 8
// speedup vs baseline: 1.7204x; 1.7106x over previous
#include <cuda_runtime.h>
#include <cuda_bf16.h>
#include <math.h>

typedef unsigned long long u64;
typedef unsigned int u32;

// ---------------------------------------------------------------------------
// Scratch (allocation-free: __device__ globals)
// ---------------------------------------------------------------------------
#define MAXN 4096
__device__ __align__(16) __nv_bfloat16 g_h1bf[MAXN * 196 * 64]; // conv1 out [n][pos196][hi32|lo32]
__device__ __align__(16) float g_h2[MAXN * 3136];               // conv2 out [n][pos49*64+co]
__device__ __align__(16) float g_fc[MAXN * 32];                 // FC out (N,32)
__device__ __align__(16) float g_fcw[3136 * 32];                // fc_w transposed [pos*64+co][d]
// conv2 weights: [split(hi/lo)][tap9][k32][n64] bf16, chunk-swizzled rows (576 rows x 128B)
__device__ __align__(16) __nv_bfloat16 g_w2bf[2 * 9 * 32 * 64];

// ---------------------------------------------------------------------------
// Warp-MMA helpers (sm_80+ path; works on plain sm_100 target)
// ---------------------------------------------------------------------------
__device__ __forceinline__ u32 smem_to_u32(const void* p) {
    u32 a;
    asm("{ .reg .u64 t; cvta.to.shared.u64 t, %1; cvt.u32.u64 %0, t; }"
        : "=r"(a) : "l"(p));
    return a;
}

__device__ __forceinline__ void ldsm_x4(u32* r, u32 addr) {
    asm volatile("ldmatrix.sync.aligned.m8n8.x4.shared.b16 {%0,%1,%2,%3}, [%4];"
        : "=r"(r[0]), "=r"(r[1]), "=r"(r[2]), "=r"(r[3]) : "r"(addr));
}
__device__ __forceinline__ void ldsm_x4_t(u32* r, u32 addr) {
    asm volatile("ldmatrix.sync.aligned.m8n8.x4.trans.shared.b16 {%0,%1,%2,%3}, [%4];"
        : "=r"(r[0]), "=r"(r[1]), "=r"(r[2]), "=r"(r[3]) : "r"(addr));
}
__device__ __forceinline__ void mma_bf16(float* c, const u32* a, const u32* b) {
    asm volatile(
        "mma.sync.aligned.m16n8k16.row.col.f32.bf16.bf16.f32 "
        "{%0,%1,%2,%3}, {%4,%5,%6,%7}, {%8,%9}, {%0,%1,%2,%3};"
        : "+f"(c[0]), "+f"(c[1]), "+f"(c[2]), "+f"(c[3])
        : "r"(a[0]), "r"(a[1]), "r"(a[2]), "r"(a[3]), "r"(b[0]), "r"(b[1]));
}

// ---------------------------------------------------------------------------
// Kernel 1: conv1 (1->32, 3x3, pad 1) + relu + maxpool2 -> bf16 hi/lo
// Output: g_h1bf[n][pos=py*14+px][hi(ci 0..31) | lo(ci 0..31)]
// ---------------------------------------------------------------------------
__global__ __launch_bounds__(256)
void conv1_kernel(const float* __restrict__ x,
                  const float* __restrict__ w,      // (32,1,3,3)
                  const float* __restrict__ bias)   // (32,)
{
    __shared__ __align__(16) float s_in[30 * 30];
    __shared__ __align__(16) float s_w[9 * 32];
    __shared__ float s_b[32];

    const int n   = blockIdx.x;
    const int tid = threadIdx.x;

    for (int i = tid; i < 900; i += 256) s_in[i] = 0.0f;
    for (int i = tid; i < 288; i += 256) {
        int co = i / 9, k = i % 9;
        s_w[k * 32 + co] = w[co * 9 + k];
    }
    if (tid < 32) s_b[tid] = bias[tid];
    __syncthreads();

    const float* xb = x + (size_t)n * 784;
    for (int i = tid; i < 784; i += 256) {
        int y = i / 28, c = i % 28;
        s_in[(y + 1) * 30 + (c + 1)] = xb[i];
    }
    __syncthreads();

    const float2* s_w2 = reinterpret_cast<const float2*>(s_w);
    __nv_bfloat162* ob = reinterpret_cast<__nv_bfloat162*>(g_h1bf) + (size_t)n * 6272;

    for (int it = tid; it < 3136; it += 256) {
        const int pair = it & 15;
        const int pos  = it >> 4;
        const int py   = pos / 14;
        const int px   = pos - py * 14;

        float pv[4][4];
#pragma unroll
        for (int r = 0; r < 4; r++)
#pragma unroll
            for (int c = 0; c < 4; c++)
                pv[r][c] = s_in[(2 * py + r) * 30 + (2 * px + c)];

        float2 bb = make_float2(s_b[pair * 2], s_b[pair * 2 + 1]);
        float a0x = bb.x, a0y = bb.y, a1x = bb.x, a1y = bb.y;
        float a2x = bb.x, a2y = bb.y, a3x = bb.x, a3y = bb.y;

#pragma unroll
        for (int ky = 0; ky < 3; ky++)
#pragma unroll
            for (int kx = 0; kx < 3; kx++) {
                float2 wf = s_w2[(ky * 3 + kx) * 16 + pair];
                float p00 = pv[ky][kx],     p01 = pv[ky][kx + 1];
                float p10 = pv[ky + 1][kx], p11 = pv[ky + 1][kx + 1];
                a0x = fmaf(p00, wf.x, a0x); a0y = fmaf(p00, wf.y, a0y);
                a1x = fmaf(p01, wf.x, a1x); a1y = fmaf(p01, wf.y, a1y);
                a2x = fmaf(p10, wf.x, a2x); a2y = fmaf(p10, wf.y, a2y);
                a3x = fmaf(p11, wf.x, a3x); a3y = fmaf(p11, wf.y, a3y);
            }

        float mlo = fmaxf(fmaxf(fmaxf(a0x, a1x), fmaxf(a2x, a3x)), 0.0f);
        float mhi = fmaxf(fmaxf(fmaxf(a0y, a1y), fmaxf(a2y, a3y)), 0.0f);

        __nv_bfloat16 hx = __float2bfloat16(mlo);
        __nv_bfloat16 hy = __float2bfloat16(mhi);
        __nv_bfloat16 lx = __float2bfloat16(mlo - __bfloat162float(hx));
        __nv_bfloat16 ly = __float2bfloat16(mhi - __bfloat162float(hy));
        __nv_bfloat162 hv; hv.x = hx; hv.y = hy;
        __nv_bfloat162 lv; lv.x = lx; lv.y = ly;
        ob[pos * 32 + pair]      = hv;
        ob[pos * 32 + 16 + pair] = lv;
    }
}

// ---------------------------------------------------------------------------
// Prep: conv2 weights -> bf16 hi/lo in [split][tap][k(ci)][n(co)] layout,
// rows of 128B with chunk swizzle: chunk c stored at (c ^ (k&7)).
// ---------------------------------------------------------------------------
__global__ void prep_w2(const float* __restrict__ w2)   // <<<9, 512>>>
{
    int t = blockIdx.x * 512 + threadIdx.x;    // 0..4607
    if (t >= 4608) return;
    int chunk = t & 7;
    int row   = t >> 3;                        // 0..575
    int k     = row & 31;
    int tap   = (row >> 5) % 9;
    int p     = row / 288;                     // 0 = hi, 1 = lo

    __nv_bfloat16 vals[8];
#pragma unroll
    for (int j = 0; j < 8; j++) {
        int co = chunk * 8 + j;
        float v = w2[co * 288 + k * 9 + tap];
        __nv_bfloat16 h = __float2bfloat16(v);
        vals[j] = p ? __float2bfloat16(v - __bfloat162float(h)) : h;
    }
    char* base = reinterpret_cast<char*>(g_w2bf);
    *reinterpret_cast<uint4*>(base + row * 128 + ((chunk ^ (k & 7)) << 4)) =
        *reinterpret_cast<const uint4*>(vals);
}

// ---------------------------------------------------------------------------
// Prep: transpose fc_w into [k'=pos*64+co][d]
// ---------------------------------------------------------------------------
__global__ void prep_fcw(const float* __restrict__ fw)  // <<<98, 1024>>>
{
    int idx = blockIdx.x * 1024 + threadIdx.x;
    if (idx >= 3136 * 32) return;
    int kp = idx >> 5, d = idx & 31;
    int pos = kp >> 6, co = kp & 63;
    g_fcw[idx] = fw[d * 3136 + co * 49 + pos];
}

// ---------------------------------------------------------------------------
// Kernel 2: conv2 via warp-level bf16 split MMA + relu + maxpool
// grid = 148 CTAs, 256 threads (8 warps), images strided.
// SMEM: bias[64]f @0; A 290x128B @1024; B 576x128B @38144; D 256x256B @111872
// ---------------------------------------------------------------------------
#define C2_BIAS_OFF 0
#define C2_A_OFF    1024
#define C2_B_OFF    (1024 + 290 * 128)          // 38144
#define C2_D_OFF    (C2_B_OFF + 576 * 128)      // 111872
#define C2_SMEM_BYTES (C2_D_OFF + 256 * 256)    // 177408

__global__ __launch_bounds__(256, 1)
void conv2_mma_kernel(const float* __restrict__ bias, int N)
{
    extern __shared__ __align__(16) char smem[];
    const u32 sb  = smem_to_u32(smem);
    const int tid = threadIdx.x;
    const int w   = tid >> 5;
    const u32 lane = tid & 31;
    const u32 lrow = lane & 15, lsel = lane >> 4;

    float* s_bias = reinterpret_cast<float*>(smem + C2_BIAS_OFF);
    if (tid < 64) s_bias[tid] = bias[tid];

    // zero whole A buffer once (pads + border rows stay zero forever)
    for (int i = tid; i < 2320; i += 256)
        reinterpret_cast<uint4*>(smem + C2_A_OFF)[i] = make_uint4(0, 0, 0, 0);

    // copy pre-swizzled weights once per CTA
    for (int i = tid; i < 4608; i += 256)
        reinterpret_cast<uint4*>(smem + C2_B_OFF)[i] =
            reinterpret_cast<const uint4*>(g_w2bf)[i];
    __syncthreads();

    const u32 Abase = sb + C2_A_OFF;
    const u32 Bbase = sb + C2_B_OFF;

    for (int img = blockIdx.x; img < N; img += gridDim.x) {
        // ---- build A interior: 196 rows x 8 chunks (swizzled) ----
        const uint4* src = reinterpret_cast<const uint4*>(g_h1bf + (size_t)img * 12544);
        for (int i = tid; i < 1568; i += 256) {
            int pos = i >> 3, chunk = i & 7;
            int py = pos / 14, px = pos - py * 14;
            int row = (py + 1) * 16 + (px + 1) + 17;     // +17 pad margin
            *reinterpret_cast<uint4*>(smem + C2_A_OFF + row * 128 +
                                      ((chunk ^ (row & 7)) << 4)) = src[i];
        }
        __syncthreads();

        // ---- MMA: warp w owns m-tiles {2w, 2w+1}, all 8 n-tiles ----
        float C[2][8][4];
#pragma unroll
        for (int mt = 0; mt < 2; mt++)
#pragma unroll
            for (int nt = 0; nt < 8; nt++)
#pragma unroll
                for (int q = 0; q < 4; q++) C[mt][nt][q] = 0.0f;

#pragma unroll 1
        for (int p = 0; p < 3; p++) {
            const u32 ah = (p == 1) ? 4u : 0u;       // A lo-half chunk offset
            const u32 bb = (p == 2) ? 288u : 0u;     // B lo-buffer row offset
#pragma unroll 1
            for (int tap = 0; tap < 9; tap++) {
                const u32 rowoff = (u32)((tap / 3) * 16 + (tap % 3));
#pragma unroll
                for (int s = 0; s < 2; s++) {
                    u32 a[2][4];
#pragma unroll
                    for (int mt = 0; mt < 2; mt++) {
                        u32 arow = (u32)((2 * w + mt) * 16) + lrow + rowoff;
                        u32 achunk = ah + (u32)(s * 2) + lsel;
                        ldsm_x4(a[mt], Abase + arow * 128 +
                                       ((achunk ^ (arow & 7)) << 4));
                    }
                    u32 b[4][4];
#pragma unroll
                    for (int nt2 = 0; nt2 < 4; nt2++) {
                        u32 krow = bb + (u32)(tap * 32 + s * 16) + lrow;
                        u32 bchunk = (u32)(nt2 * 2) + lsel;
                        ldsm_x4_t(b[nt2], Bbase + krow * 128 +
                                          ((bchunk ^ (krow & 7)) << 4));
                    }
#pragma unroll
                    for (int mt = 0; mt < 2; mt++)
#pragma unroll
                        for (int nt = 0; nt < 8; nt++)
                            mma_bf16(C[mt][nt], a[mt], &b[nt >> 1][(nt & 1) * 2]);
                }
            }
        }

        // ---- stage D[256][64] f32 in smem ----
        {
            const int r0 = (int)(lane >> 2);
            const int nb = (int)(lane & 3) * 2;
#pragma unroll
            for (int mt = 0; mt < 2; mt++) {
                int m = (2 * w + mt) * 16 + r0;
#pragma unroll
                for (int nt = 0; nt < 8; nt++) {
                    int n = nt * 8 + nb;
                    float2* d0 = reinterpret_cast<float2*>(
                        smem + C2_D_OFF + m * 256 + n * 4);
                    float2* d1 = reinterpret_cast<float2*>(
                        smem + C2_D_OFF + (m + 8) * 256 + n * 4);
                    *d0 = make_float2(C[mt][nt][0], C[mt][nt][1]);
                    *d1 = make_float2(C[mt][nt][2], C[mt][nt][3]);
                }
            }
        }
        __syncthreads();

        // ---- pool 2x2 + bias + relu, store float4 ----
        const float4* Dv = reinterpret_cast<const float4*>(smem + C2_D_OFF);
        for (int i = tid; i < 784; i += 256) {
            int ppos = i >> 4, q = i & 15;
            int pyo = ppos / 7, pxo = ppos - pyo * 7;
            int m00 = (2 * pyo + 1) * 16 + (2 * pxo + 1);
            float4 v0 = Dv[m00 * 16 + q];
            float4 v1 = Dv[(m00 + 1) * 16 + q];
            float4 v2 = Dv[(m00 + 16) * 16 + q];
            float4 v3 = Dv[(m00 + 17) * 16 + q];
            float4 r;
            r.x = fmaxf(fmaxf(fmaxf(v0.x, v1.x), fmaxf(v2.x, v3.x)) + s_bias[q * 4 + 0], 0.0f);
            r.y = fmaxf(fmaxf(fmaxf(v0.y, v1.y), fmaxf(v2.y, v3.y)) + s_bias[q * 4 + 1], 0.0f);
            r.z = fmaxf(fmaxf(fmaxf(v0.z, v1.z), fmaxf(v2.z, v3.z)) + s_bias[q * 4 + 2], 0.0f);
            r.w = fmaxf(fmaxf(fmaxf(v0.w, v1.w), fmaxf(v2.w, v3.w)) + s_bias[q * 4 + 3], 0.0f);
            *reinterpret_cast<float4*>(g_h2 + (size_t)img * 3136 + ppos * 64 + q * 4) = r;
        }
        __syncthreads();
    }
}

// ---------------------------------------------------------------------------
// Kernel 3: FC  (N,3136) @ w'[3136,32] + bias -> (N,32)
// ---------------------------------------------------------------------------
#define FC_KT 112

__global__ __launch_bounds__(256)
void fc_kernel(const float* __restrict__ bias)
{
    __shared__ __align__(16) float a_s[32 * FC_KT];
    __shared__ float b_s[FC_KT * 33];

    const int tid = threadIdx.x;
    const int n0  = blockIdx.x * 32;
    const int d   = tid & 31;
    const int tr  = tid >> 5;

    float acc[4];
    float bv = bias[d];
#pragma unroll
    for (int i = 0; i < 4; i++) acc[i] = bv;

    for (int kt = 0; kt < 3136; kt += FC_KT) {
        __syncthreads();
        for (int i = tid; i < 32 * FC_KT; i += 256) {
            int r = i / FC_KT, c = i - r * FC_KT;
            a_s[r * FC_KT + c] = g_h2[(size_t)(n0 + r) * 3136 + kt + c];
        }
        for (int i = tid; i < 32 * FC_KT; i += 256) {
            int c = i >> 5, dd = i & 31;
            b_s[c * 33 + dd] = g_fcw[(size_t)(kt + c) * 32 + dd];
        }
        __syncthreads();

#pragma unroll 4
        for (int kk = 0; kk < FC_KT; kk += 4) {
            float w0 = b_s[(kk + 0) * 33 + d];
            float w1 = b_s[(kk + 1) * 33 + d];
            float w2 = b_s[(kk + 2) * 33 + d];
            float w3 = b_s[(kk + 3) * 33 + d];
#pragma unroll
            for (int i = 0; i < 4; i++) {
                float4 av = *reinterpret_cast<const float4*>(
                    a_s + (tr * 4 + i) * FC_KT + kk);
                acc[i] = fmaf(av.x, w0, acc[i]);
                acc[i] = fmaf(av.y, w1, acc[i]);
                acc[i] = fmaf(av.z, w2, acc[i]);
                acc[i] = fmaf(av.w, w3, acc[i]);
            }
        }
    }

#pragma unroll
    for (int i = 0; i < 4; i++)
        g_fc[(size_t)(n0 + tr * 4 + i) * 32 + d] = acc[i];
}

// ---------------------------------------------------------------------------
// Kernel 4: hyperbolic MLR  (N,32) -> (N,10), c = 1
// ---------------------------------------------------------------------------
__global__ __launch_bounds__(256)
void mlr_kernel(const float* __restrict__ hw,
                const float* __restrict__ hb,
                float* __restrict__ out, int total)
{
    int i = blockIdx.x * blockDim.x + threadIdx.x;
    if (i >= total) return;
    int n = i / 10;
    int k = i - n * 10;

    const float* xv = g_fc + (size_t)n * 32;
    const float* wv = hw + k * 32;
    const float* bv = hb + k * 32;

    float x2 = 0.f, b2 = 0.f, w2 = 0.f, xb = 0.f, xw = 0.f, wb = 0.f;
#pragma unroll
    for (int j = 0; j < 32; j++) {
        float xj = xv[j], wj = wv[j], bj = bv[j];
        x2 += xj * xj;  b2 += bj * bj;  w2 += wj * wj;
        xb += xj * bj;  xw += xj * wj;  wb += wj * bj;
    }

    const float EPSf = 1e-5f;
    const float MN   = 0.99999f;

    float inner  = -xb;
    float w_norm = sqrtf(w2);
    float inv_wn = 1.0f / fmaxf(w_norm, 1e-12f);
    float wb_n   = -wb * inv_wn;
    float xw_n   = xw * inv_wn;

    float a_num = 1.0f + 2.0f * inner + x2;
    float b_num = 1.0f - b2;
    float denom = 1.0f + 2.0f * inner + x2 * b2;
    float alpha = a_num / fmaxf(denom, EPSf);
    float beta  = b_num / denom;
    float mob2  = alpha * alpha * b2 + 2.0f * alpha * beta * inner
                + beta * beta * x2;
    float sq    = sqrtf(mob2);
    float normalizer = (sq > MN) ? (MN / fmaxf(sq, EPSf)) : 1.0f;
    float mob2f = (sq < MN) ? mob2 : (MN * MN);
    float hyp   = (alpha * wb_n + beta * xw_n) * normalizer;
    float asin_in = 2.0f * hyp / fmaxf(1.0f - mob2f, EPSf);

    out[i] = (2.0f / fmaxf(1.0f - b2, EPSf)) * w_norm * asinhf(asin_in);
}

// ---------------------------------------------------------------------------
// Launch
// ---------------------------------------------------------------------------
extern "C" void kernel_launch(void* const* d_in, const int* in_sizes, int n_in,
                              void* d_out, int out_size) {
    const float* x   = (const float*)d_in[0];
    const float* w1  = (const float*)d_in[1];
    const float* b1  = (const float*)d_in[2];
    const float* w2  = (const float*)d_in[3];
    const float* b2  = (const float*)d_in[4];
    const float* fw  = (const float*)d_in[5];
    const float* fb  = (const float*)d_in[6];
    const float* hw  = (const float*)d_in[7];
    const float* hb  = (const float*)d_in[8];
    float* out = (float*)d_out;

    const int N = in_sizes[0] / 784;

    cudaFuncSetAttribute(conv2_mma_kernel,
                         cudaFuncAttributeMaxDynamicSharedMemorySize,
                         C2_SMEM_BYTES);

    prep_w2<<<9, 512>>>(w2);
    prep_fcw<<<98, 1024>>>(fw);
    conv1_kernel<<<N, 256>>>(x, w1, b1);
    int g2 = N < 148 ? N : 148;
    conv2_mma_kernel<<<g2, 256, C2_SMEM_BYTES>>>(b2, N);
    fc_kernel<<<N / 32, 256>>>(fb);
    int total = N * 10;
    mlr_kernel<<<(total + 255) / 256, 256>>>(hw, hb, out, total);
}

// round 9
// speedup vs baseline: 1.7230x; 1.0015x over previous
#include <cuda_runtime.h>
#include <cuda_bf16.h>
#include <math.h>

typedef unsigned long long u64;
typedef unsigned int u32;

// ---------------------------------------------------------------------------
// Scratch (allocation-free: __device__ globals)
// ---------------------------------------------------------------------------
#define MAXN 4096
__device__ __align__(16) __nv_bfloat16 g_h1bf[MAXN * 196 * 64]; // conv1 out [n][pos196][hi32|lo32]
__device__ __align__(16) float g_h2[MAXN * 3136];               // conv2 out [n][pos49*64+co]
__device__ __align__(16) float g_fc[MAXN * 32];                 // FC out (N,32)
__device__ __align__(16) float g_fcw[3136 * 32];                // fc_w transposed [pos*64+co][d]
// conv2 weights: [split(hi/lo)][tap9][k32][n64] bf16, chunk-swizzled rows (576 rows x 128B)
__device__ __align__(16) __nv_bfloat16 g_w2bf[2 * 9 * 32 * 64];

// ---------------------------------------------------------------------------
// Warp-MMA helpers (sm_80+ path; works on plain sm_100 target)
// ---------------------------------------------------------------------------
__device__ __forceinline__ u32 smem_to_u32(const void* p) {
    u32 a;
    asm("{ .reg .u64 t; cvta.to.shared.u64 t, %1; cvt.u32.u64 %0, t; }"
        : "=r"(a) : "l"(p));
    return a;
}
__device__ __forceinline__ void ldsm_x4(u32* r, u32 addr) {
    asm volatile("ldmatrix.sync.aligned.m8n8.x4.shared.b16 {%0,%1,%2,%3}, [%4];"
        : "=r"(r[0]), "=r"(r[1]), "=r"(r[2]), "=r"(r[3]) : "r"(addr));
}
__device__ __forceinline__ void ldsm_x4_t(u32* r, u32 addr) {
    asm volatile("ldmatrix.sync.aligned.m8n8.x4.trans.shared.b16 {%0,%1,%2,%3}, [%4];"
        : "=r"(r[0]), "=r"(r[1]), "=r"(r[2]), "=r"(r[3]) : "r"(addr));
}
__device__ __forceinline__ void mma_bf16(float* c, const u32* a, const u32* b) {
    asm volatile(
        "mma.sync.aligned.m16n8k16.row.col.f32.bf16.bf16.f32 "
        "{%0,%1,%2,%3}, {%4,%5,%6,%7}, {%8,%9}, {%0,%1,%2,%3};"
        : "+f"(c[0]), "+f"(c[1]), "+f"(c[2]), "+f"(c[3])
        : "r"(a[0]), "r"(a[1]), "r"(a[2]), "r"(a[3]), "r"(b[0]), "r"(b[1]));
}

// ---------------------------------------------------------------------------
// Kernel 1: conv1 (1->32, 3x3, pad 1) + relu + maxpool2 -> bf16 hi/lo
// Output: g_h1bf[n][pos=py*14+px][hi(ci 0..31) | lo(ci 0..31)]
// ---------------------------------------------------------------------------
__global__ __launch_bounds__(256)
void conv1_kernel(const float* __restrict__ x,
                  const float* __restrict__ w,      // (32,1,3,3)
                  const float* __restrict__ bias)   // (32,)
{
    __shared__ __align__(16) float s_in[30 * 30];
    __shared__ __align__(16) float s_w[9 * 32];
    __shared__ float s_b[32];

    const int n   = blockIdx.x;
    const int tid = threadIdx.x;

    for (int i = tid; i < 900; i += 256) s_in[i] = 0.0f;
    for (int i = tid; i < 288; i += 256) {
        int co = i / 9, k = i % 9;
        s_w[k * 32 + co] = w[co * 9 + k];
    }
    if (tid < 32) s_b[tid] = bias[tid];
    __syncthreads();

    const float* xb = x + (size_t)n * 784;
    for (int i = tid; i < 784; i += 256) {
        int y = i / 28, c = i % 28;
        s_in[(y + 1) * 30 + (c + 1)] = xb[i];
    }
    __syncthreads();

    const float2* s_w2 = reinterpret_cast<const float2*>(s_w);
    __nv_bfloat162* ob = reinterpret_cast<__nv_bfloat162*>(g_h1bf) + (size_t)n * 6272;

    for (int it = tid; it < 3136; it += 256) {
        const int pair = it & 15;
        const int pos  = it >> 4;
        const int py   = pos / 14;
        const int px   = pos - py * 14;

        float pv[4][4];
#pragma unroll
        for (int r = 0; r < 4; r++)
#pragma unroll
            for (int c = 0; c < 4; c++)
                pv[r][c] = s_in[(2 * py + r) * 30 + (2 * px + c)];

        float2 bb = make_float2(s_b[pair * 2], s_b[pair * 2 + 1]);
        float a0x = bb.x, a0y = bb.y, a1x = bb.x, a1y = bb.y;
        float a2x = bb.x, a2y = bb.y, a3x = bb.x, a3y = bb.y;

#pragma unroll
        for (int ky = 0; ky < 3; ky++)
#pragma unroll
            for (int kx = 0; kx < 3; kx++) {
                float2 wf = s_w2[(ky * 3 + kx) * 16 + pair];
                float p00 = pv[ky][kx],     p01 = pv[ky][kx + 1];
                float p10 = pv[ky + 1][kx], p11 = pv[ky + 1][kx + 1];
                a0x = fmaf(p00, wf.x, a0x); a0y = fmaf(p00, wf.y, a0y);
                a1x = fmaf(p01, wf.x, a1x); a1y = fmaf(p01, wf.y, a1y);
                a2x = fmaf(p10, wf.x, a2x); a2y = fmaf(p10, wf.y, a2y);
                a3x = fmaf(p11, wf.x, a3x); a3y = fmaf(p11, wf.y, a3y);
            }

        float mlo = fmaxf(fmaxf(fmaxf(a0x, a1x), fmaxf(a2x, a3x)), 0.0f);
        float mhi = fmaxf(fmaxf(fmaxf(a0y, a1y), fmaxf(a2y, a3y)), 0.0f);

        __nv_bfloat16 hx = __float2bfloat16(mlo);
        __nv_bfloat16 hy = __float2bfloat16(mhi);
        __nv_bfloat16 lx = __float2bfloat16(mlo - __bfloat162float(hx));
        __nv_bfloat16 ly = __float2bfloat16(mhi - __bfloat162float(hy));
        __nv_bfloat162 hv; hv.x = hx; hv.y = hy;
        __nv_bfloat162 lv; lv.x = lx; lv.y = ly;
        ob[pos * 32 + pair]      = hv;
        ob[pos * 32 + 16 + pair] = lv;
    }
}

// ---------------------------------------------------------------------------
// Prep: conv2 weights -> bf16 hi/lo in [split][tap][k(ci)][n(co)] layout,
// rows of 128B with chunk swizzle: chunk c stored at (c ^ (k&7)).
// ---------------------------------------------------------------------------
__global__ void prep_w2(const float* __restrict__ w2)   // <<<9, 512>>>
{
    int t = blockIdx.x * 512 + threadIdx.x;
    if (t >= 4608) return;
    int chunk = t & 7;
    int row   = t >> 3;
    int k     = row & 31;
    int tap   = (row >> 5) % 9;
    int p     = row / 288;

    __nv_bfloat16 vals[8];
#pragma unroll
    for (int j = 0; j < 8; j++) {
        int co = chunk * 8 + j;
        float v = w2[co * 288 + k * 9 + tap];
        __nv_bfloat16 h = __float2bfloat16(v);
        vals[j] = p ? __float2bfloat16(v - __bfloat162float(h)) : h;
    }
    char* base = reinterpret_cast<char*>(g_w2bf);
    *reinterpret_cast<uint4*>(base + row * 128 + ((chunk ^ (k & 7)) << 4)) =
        *reinterpret_cast<const uint4*>(vals);
}

// ---------------------------------------------------------------------------
// Prep: transpose fc_w into [k'=pos*64+co][d]
// ---------------------------------------------------------------------------
__global__ void prep_fcw(const float* __restrict__ fw)  // <<<98, 1024>>>
{
    int idx = blockIdx.x * 1024 + threadIdx.x;
    if (idx >= 3136 * 32) return;
    int kp = idx >> 5, d = idx & 31;
    int pos = kp >> 6, co = kp & 63;
    g_fcw[idx] = fw[d * 3136 + co * 49 + pos];
}

// ---------------------------------------------------------------------------
// Kernel 2: conv2 warp-MMA, 2 images per iteration, register-pooled epilogue.
// Warp w (0..6) = pooled row; computes m-tiles {2w+1, 2w+2} of both images.
// SMEM: bias @0 (256B); A0 @1024, A1 @38144 (290x128B each); B @75264 (576x128B)
// ---------------------------------------------------------------------------
#define C2_BIAS_OFF 0
#define C2_A0_OFF   1024
#define C2_A_BYTES  (290 * 128)
#define C2_B_OFF    (C2_A0_OFF + 2 * C2_A_BYTES)     // 75264
#define C2_SMEM_BYTES (C2_B_OFF + 576 * 128)         // 148992

__global__ __launch_bounds__(256, 1)
void conv2_mma_kernel(const float* __restrict__ bias, int N)
{
    extern __shared__ __align__(16) char smem[];
    const u32 sb   = smem_to_u32(smem);
    const int tid  = threadIdx.x;
    const int w    = tid >> 5;
    const u32 lane = tid & 31;
    const u32 lrow = lane & 15, lsel = lane >> 4;
    const int g    = (int)(lane >> 2);
    const int kq   = (int)(lane & 3);

    float* s_bias = reinterpret_cast<float*>(smem + C2_BIAS_OFF);
    if (tid < 64) s_bias[tid] = bias[tid];

    // zero both A buffers (pads stay zero forever)
    for (int i = tid; i < 2 * 2320; i += 256)
        reinterpret_cast<uint4*>(smem + C2_A0_OFF)[i] = make_uint4(0, 0, 0, 0);
    // copy pre-swizzled weights once per CTA
    for (int i = tid; i < 4608; i += 256)
        reinterpret_cast<uint4*>(smem + C2_B_OFF)[i] =
            reinterpret_cast<const uint4*>(g_w2bf)[i];
    __syncthreads();

    const u32 Bbase = sb + C2_B_OFF;

    for (int base = blockIdx.x * 2; base < N; base += (int)gridDim.x * 2) {
        // ---- build A interior for both images ----
#pragma unroll
        for (int u = 0; u < 2; u++) {
            int img = base + u;
            if (img >= N) break;
            const uint4* src = reinterpret_cast<const uint4*>(g_h1bf + (size_t)img * 12544);
            for (int i = tid; i < 1568; i += 256) {
                int pos = i >> 3, chunk = i & 7;
                int py = pos / 14, px = pos - py * 14;
                int row = (py + 1) * 16 + (px + 1) + 17;
                *reinterpret_cast<uint4*>(smem + C2_A0_OFF + u * C2_A_BYTES + row * 128 +
                                          ((chunk ^ (row & 7)) << 4)) = src[i];
            }
        }
        __syncthreads();

        if (w < 7) {
            float C[2][2][8][4];
#pragma unroll
            for (int u = 0; u < 2; u++)
#pragma unroll
                for (int mt = 0; mt < 2; mt++)
#pragma unroll
                    for (int nt = 0; nt < 8; nt++)
#pragma unroll
                        for (int q = 0; q < 4; q++) C[u][mt][nt][q] = 0.0f;

#pragma unroll 1
            for (int tap = 0; tap < 9; tap++) {
                const u32 rowoff = (u32)((tap / 3) * 16 + (tap % 3));
#pragma unroll
                for (int s = 0; s < 2; s++) {
                    // B-hi fragments (shared by p=0 and p=1)
                    u32 bh[4][4];
#pragma unroll
                    for (int nt2 = 0; nt2 < 4; nt2++) {
                        u32 krow = (u32)(tap * 32 + s * 16) + lrow;
                        u32 bchunk = (u32)(nt2 * 2) + lsel;
                        ldsm_x4_t(bh[nt2], Bbase + krow * 128 + ((bchunk ^ (krow & 7)) << 4));
                    }
                    // A-hi fragments
                    u32 ah[2][2][4];
#pragma unroll
                    for (int u = 0; u < 2; u++)
#pragma unroll
                        for (int mt = 0; mt < 2; mt++) {
                            u32 arow = (u32)((2 * w + 1 + mt) * 16) + lrow + rowoff;
                            u32 achunk = (u32)(s * 2) + lsel;
                            ldsm_x4(ah[u][mt], sb + C2_A0_OFF + u * C2_A_BYTES + arow * 128 +
                                               ((achunk ^ (arow & 7)) << 4));
                        }
                    // p0: Ah x Bh
#pragma unroll
                    for (int u = 0; u < 2; u++)
#pragma unroll
                        for (int mt = 0; mt < 2; mt++)
#pragma unroll
                            for (int nt = 0; nt < 8; nt++)
                                mma_bf16(C[u][mt][nt], ah[u][mt], &bh[nt >> 1][(nt & 1) * 2]);
                    // A-lo fragments, p1: Al x Bh
                    u32 al[2][2][4];
#pragma unroll
                    for (int u = 0; u < 2; u++)
#pragma unroll
                        for (int mt = 0; mt < 2; mt++) {
                            u32 arow = (u32)((2 * w + 1 + mt) * 16) + lrow + rowoff;
                            u32 achunk = 4u + (u32)(s * 2) + lsel;
                            ldsm_x4(al[u][mt], sb + C2_A0_OFF + u * C2_A_BYTES + arow * 128 +
                                               ((achunk ^ (arow & 7)) << 4));
                        }
#pragma unroll
                    for (int u = 0; u < 2; u++)
#pragma unroll
                        for (int mt = 0; mt < 2; mt++)
#pragma unroll
                            for (int nt = 0; nt < 8; nt++)
                                mma_bf16(C[u][mt][nt], al[u][mt], &bh[nt >> 1][(nt & 1) * 2]);
                    // B-lo fragments, p2: Ah x Bl
                    u32 bl[4][4];
#pragma unroll
                    for (int nt2 = 0; nt2 < 4; nt2++) {
                        u32 krow = 288u + (u32)(tap * 32 + s * 16) + lrow;
                        u32 bchunk = (u32)(nt2 * 2) + lsel;
                        ldsm_x4_t(bl[nt2], Bbase + krow * 128 + ((bchunk ^ (krow & 7)) << 4));
                    }
#pragma unroll
                    for (int u = 0; u < 2; u++)
#pragma unroll
                        for (int mt = 0; mt < 2; mt++)
#pragma unroll
                            for (int nt = 0; nt < 8; nt++)
                                mma_bf16(C[u][mt][nt], ah[u][mt], &bl[nt >> 1][(nt & 1) * 2]);
                }
            }

            // ---- register epilogue: y-pool (mt max) + x-pool (shuffles) ----
#pragma unroll
            for (int u = 0; u < 2; u++) {
                int img = base + u;
                if (img >= N) break;
                float* outb = g_h2 + (size_t)img * 3136;
#pragma unroll
                for (int nt = 0; nt < 8; nt++) {
                    float p0 = fmaxf(C[u][0][nt][0], C[u][1][nt][0]);
                    float p1 = fmaxf(C[u][0][nt][1], C[u][1][nt][1]);
                    float p2 = fmaxf(C[u][0][nt][2], C[u][1][nt][2]);
                    float p3 = fmaxf(C[u][0][nt][3], C[u][1][nt][3]);
                    int srcl = (int)((lane + 4) & 31);
                    float q0 = __shfl_sync(0xffffffffu, p0, srcl);
                    float q1 = __shfl_sync(0xffffffffu, p1, srcl);
                    float q2 = __shfl_sync(0xffffffffu, p2, srcl);
                    float q3 = __shfl_sync(0xffffffffu, p3, srcl);
                    float bx = s_bias[nt * 8 + 2 * kq];
                    float by = s_bias[nt * 8 + 2 * kq + 1];

                    if (g == 1 || g == 3 || g == 5) {
                        int pxo = (g - 1) >> 1;
                        float2 r0;
                        r0.x = fmaxf(fmaxf(p0, q0) + bx, 0.0f);
                        r0.y = fmaxf(fmaxf(p1, q1) + by, 0.0f);
                        *reinterpret_cast<float2*>(outb + (w * 7 + pxo) * 64 + nt * 8 + 2 * kq) = r0;
                        float2 r1;
                        r1.x = fmaxf(fmaxf(p2, q2) + bx, 0.0f);
                        r1.y = fmaxf(fmaxf(p3, q3) + by, 0.0f);
                        *reinterpret_cast<float2*>(outb + (w * 7 + pxo + 4) * 64 + nt * 8 + 2 * kq) = r1;
                    } else if (g == 7) {
                        float2 r0;
                        r0.x = fmaxf(fmaxf(p0, q2) + bx, 0.0f);
                        r0.y = fmaxf(fmaxf(p1, q3) + by, 0.0f);
                        *reinterpret_cast<float2*>(outb + (w * 7 + 3) * 64 + nt * 8 + 2 * kq) = r0;
                    }
                }
            }
        }
        __syncthreads();
    }
}

// ---------------------------------------------------------------------------
// Kernel 3: FC  (N,3136) @ w'[3136,32] + bias -> (N,32)
// ---------------------------------------------------------------------------
#define FC_KT 112

__global__ __launch_bounds__(256)
void fc_kernel(const float* __restrict__ bias)
{
    __shared__ __align__(16) float a_s[32 * FC_KT];
    __shared__ float b_s[FC_KT * 33];

    const int tid = threadIdx.x;
    const int n0  = blockIdx.x * 32;
    const int d   = tid & 31;
    const int tr  = tid >> 5;

    float acc[4];
    float bv = bias[d];
#pragma unroll
    for (int i = 0; i < 4; i++) acc[i] = bv;

    for (int kt = 0; kt < 3136; kt += FC_KT) {
        __syncthreads();
        for (int i = tid; i < 32 * FC_KT; i += 256) {
            int r = i / FC_KT, c = i - r * FC_KT;
            a_s[r * FC_KT + c] = g_h2[(size_t)(n0 + r) * 3136 + kt + c];
        }
        for (int i = tid; i < 32 * FC_KT; i += 256) {
            int c = i >> 5, dd = i & 31;
            b_s[c * 33 + dd] = g_fcw[(size_t)(kt + c) * 32 + dd];
        }
        __syncthreads();

#pragma unroll 4
        for (int kk = 0; kk < FC_KT; kk += 4) {
            float w0 = b_s[(kk + 0) * 33 + d];
            float w1 = b_s[(kk + 1) * 33 + d];
            float w2 = b_s[(kk + 2) * 33 + d];
            float w3 = b_s[(kk + 3) * 33 + d];
#pragma unroll
            for (int i = 0; i < 4; i++) {
                float4 av = *reinterpret_cast<const float4*>(
                    a_s + (tr * 4 + i) * FC_KT + kk);
                acc[i] = fmaf(av.x, w0, acc[i]);
                acc[i] = fmaf(av.y, w1, acc[i]);
                acc[i] = fmaf(av.z, w2, acc[i]);
                acc[i] = fmaf(av.w, w3, acc[i]);
            }
        }
    }

#pragma unroll
    for (int i = 0; i < 4; i++)
        g_fc[(size_t)(n0 + tr * 4 + i) * 32 + d] = acc[i];
}

// ---------------------------------------------------------------------------
// Kernel 4: hyperbolic MLR  (N,32) -> (N,10), c = 1
// ---------------------------------------------------------------------------
__global__ __launch_bounds__(256)
void mlr_kernel(const float* __restrict__ hw,
                const float* __restrict__ hb,
                float* __restrict__ out, int total)
{
    int i = blockIdx.x * blockDim.x + threadIdx.x;
    if (i >= total) return;
    int n = i / 10;
    int k = i - n * 10;

    const float* xv = g_fc + (size_t)n * 32;
    const float* wv = hw + k * 32;
    const float* bv = hb + k * 32;

    float x2 = 0.f, b2 = 0.f, w2 = 0.f, xb = 0.f, xw = 0.f, wb = 0.f;
#pragma unroll
    for (int j = 0; j < 32; j++) {
        float xj = xv[j], wj = wv[j], bj = bv[j];
        x2 += xj * xj;  b2 += bj * bj;  w2 += wj * wj;
        xb += xj * bj;  xw += xj * wj;  wb += wj * bj;
    }

    const float EPSf = 1e-5f;
    const float MN   = 0.99999f;

    float inner  = -xb;
    float w_norm = sqrtf(w2);
    float inv_wn = 1.0f / fmaxf(w_norm, 1e-12f);
    float wb_n   = -wb * inv_wn;
    float xw_n   = xw * inv_wn;

    float a_num = 1.0f + 2.0f * inner + x2;
    float b_num = 1.0f - b2;
    float denom = 1.0f + 2.0f * inner + x2 * b2;
    float alpha = a_num / fmaxf(denom, EPSf);
    float beta  = b_num / denom;
    float mob2  = alpha * alpha * b2 + 2.0f * alpha * beta * inner
                + beta * beta * x2;
    float sq    = sqrtf(mob2);
    float normalizer = (sq > MN) ? (MN / fmaxf(sq, EPSf)) : 1.0f;
    float mob2f = (sq < MN) ? mob2 : (MN * MN);
    float hyp   = (alpha * wb_n + beta * xw_n) * normalizer;
    float asin_in = 2.0f * hyp / fmaxf(1.0f - mob2f, EPSf);

    out[i] = (2.0f / fmaxf(1.0f - b2, EPSf)) * w_norm * asinhf(asin_in);
}

// ---------------------------------------------------------------------------
// Launch
// ---------------------------------------------------------------------------
extern "C" void kernel_launch(void* const* d_in, const int* in_sizes, int n_in,
                              void* d_out, int out_size) {
    const float* x   = (const float*)d_in[0];
    const float* w1  = (const float*)d_in[1];
    const float* b1  = (const float*)d_in[2];
    const float* w2  = (const float*)d_in[3];
    const float* b2  = (const float*)d_in[4];
    const float* fw  = (const float*)d_in[5];
    const float* fb  = (const float*)d_in[6];
    const float* hw  = (const float*)d_in[7];
    const float* hb  = (const float*)d_in[8];
    float* out = (float*)d_out;

    const int N = in_sizes[0] / 784;

    cudaFuncSetAttribute(conv2_mma_kernel,
                         cudaFuncAttributeMaxDynamicSharedMemorySize,
                         C2_SMEM_BYTES);

    prep_w2<<<9, 512>>>(w2);
    prep_fcw<<<98, 1024>>>(fw);
    conv1_kernel<<<N, 256>>>(x, w1, b1);
    int pairs = (N + 1) / 2;
    int g2 = pairs < 148 ? pairs : 148;
    conv2_mma_kernel<<<g2, 256, C2_SMEM_BYTES>>>(b2, N);
    fc_kernel<<<N / 32, 256>>>(fb);
    int total = N * 10;
    mlr_kernel<<<(total + 255) / 256, 256>>>(hw, hb, out, total);
}

// round 10
// speedup vs baseline: 1.8532x; 1.0756x over previous
#include <cuda_runtime.h>
#include <cuda_bf16.h>
#include <math.h>

typedef unsigned long long u64;
typedef unsigned int u32;

// ---------------------------------------------------------------------------
// Scratch (allocation-free: __device__ globals)
// ---------------------------------------------------------------------------
#define MAXN 4096
__device__ __align__(16) __nv_bfloat16 g_h1bf[MAXN * 196 * 64]; // conv1 out [n][pos196][hi32|lo32]
__device__ __align__(16) float g_h2[MAXN * 3136];               // conv2 out [n][pos49*64+co]
__device__ __align__(16) float g_fc[MAXN * 32];                 // FC out (N,32)
__device__ __align__(16) float g_fcw[3136 * 32];                // fc_w transposed [pos*64+co][d]
__device__ __align__(16) __nv_bfloat16 g_w2bf[2 * 9 * 32 * 64]; // conv2 w, swizzled

// ---------------------------------------------------------------------------
// Warp-MMA helpers
// ---------------------------------------------------------------------------
__device__ __forceinline__ u32 smem_to_u32(const void* p) {
    u32 a;
    asm("{ .reg .u64 t; cvta.to.shared.u64 t, %1; cvt.u32.u64 %0, t; }"
        : "=r"(a) : "l"(p));
    return a;
}
__device__ __forceinline__ void ldsm_x4(u32* r, u32 addr) {
    asm volatile("ldmatrix.sync.aligned.m8n8.x4.shared.b16 {%0,%1,%2,%3}, [%4];"
        : "=r"(r[0]), "=r"(r[1]), "=r"(r[2]), "=r"(r[3]) : "r"(addr));
}
__device__ __forceinline__ void ldsm_x4_t(u32* r, u32 addr) {
    asm volatile("ldmatrix.sync.aligned.m8n8.x4.trans.shared.b16 {%0,%1,%2,%3}, [%4];"
        : "=r"(r[0]), "=r"(r[1]), "=r"(r[2]), "=r"(r[3]) : "r"(addr));
}
__device__ __forceinline__ void mma_bf16(float* c, const u32* a, const u32* b) {
    asm volatile(
        "mma.sync.aligned.m16n8k16.row.col.f32.bf16.bf16.f32 "
        "{%0,%1,%2,%3}, {%4,%5,%6,%7}, {%8,%9}, {%0,%1,%2,%3};"
        : "+f"(c[0]), "+f"(c[1]), "+f"(c[2]), "+f"(c[3])
        : "r"(a[0]), "r"(a[1]), "r"(a[2]), "r"(a[3]), "r"(b[0]), "r"(b[1]));
}

// ---------------------------------------------------------------------------
// Kernel 1: conv1 (1->32, 3x3, pad 1) + relu + maxpool2 -> bf16 hi/lo
// ---------------------------------------------------------------------------
__global__ __launch_bounds__(256)
void conv1_kernel(const float* __restrict__ x,
                  const float* __restrict__ w,
                  const float* __restrict__ bias)
{
    __shared__ __align__(16) float s_in[30 * 30];
    __shared__ __align__(16) float s_w[9 * 32];
    __shared__ float s_b[32];

    const int n   = blockIdx.x;
    const int tid = threadIdx.x;

    for (int i = tid; i < 900; i += 256) s_in[i] = 0.0f;
    for (int i = tid; i < 288; i += 256) {
        int co = i / 9, k = i % 9;
        s_w[k * 32 + co] = w[co * 9 + k];
    }
    if (tid < 32) s_b[tid] = bias[tid];
    __syncthreads();

    const float* xb = x + (size_t)n * 784;
    for (int i = tid; i < 784; i += 256) {
        int y = i / 28, c = i % 28;
        s_in[(y + 1) * 30 + (c + 1)] = xb[i];
    }
    __syncthreads();

    const float2* s_w2 = reinterpret_cast<const float2*>(s_w);
    __nv_bfloat162* ob = reinterpret_cast<__nv_bfloat162*>(g_h1bf) + (size_t)n * 6272;

    for (int it = tid; it < 3136; it += 256) {
        const int pair = it & 15;
        const int pos  = it >> 4;
        const int py   = pos / 14;
        const int px   = pos - py * 14;

        float pv[4][4];
#pragma unroll
        for (int r = 0; r < 4; r++)
#pragma unroll
            for (int c = 0; c < 4; c++)
                pv[r][c] = s_in[(2 * py + r) * 30 + (2 * px + c)];

        float2 bb = make_float2(s_b[pair * 2], s_b[pair * 2 + 1]);
        float a0x = bb.x, a0y = bb.y, a1x = bb.x, a1y = bb.y;
        float a2x = bb.x, a2y = bb.y, a3x = bb.x, a3y = bb.y;

#pragma unroll
        for (int ky = 0; ky < 3; ky++)
#pragma unroll
            for (int kx = 0; kx < 3; kx++) {
                float2 wf = s_w2[(ky * 3 + kx) * 16 + pair];
                float p00 = pv[ky][kx],     p01 = pv[ky][kx + 1];
                float p10 = pv[ky + 1][kx], p11 = pv[ky + 1][kx + 1];
                a0x = fmaf(p00, wf.x, a0x); a0y = fmaf(p00, wf.y, a0y);
                a1x = fmaf(p01, wf.x, a1x); a1y = fmaf(p01, wf.y, a1y);
                a2x = fmaf(p10, wf.x, a2x); a2y = fmaf(p10, wf.y, a2y);
                a3x = fmaf(p11, wf.x, a3x); a3y = fmaf(p11, wf.y, a3y);
            }

        float mlo = fmaxf(fmaxf(fmaxf(a0x, a1x), fmaxf(a2x, a3x)), 0.0f);
        float mhi = fmaxf(fmaxf(fmaxf(a0y, a1y), fmaxf(a2y, a3y)), 0.0f);

        __nv_bfloat16 hx = __float2bfloat16(mlo);
        __nv_bfloat16 hy = __float2bfloat16(mhi);
        __nv_bfloat16 lx = __float2bfloat16(mlo - __bfloat162float(hx));
        __nv_bfloat16 ly = __float2bfloat16(mhi - __bfloat162float(hy));
        __nv_bfloat162 hv; hv.x = hx; hv.y = hy;
        __nv_bfloat162 lv; lv.x = lx; lv.y = ly;
        ob[pos * 32 + pair]      = hv;
        ob[pos * 32 + 16 + pair] = lv;
    }
}

// ---------------------------------------------------------------------------
// Prep: conv2 weights -> bf16 hi/lo, [split][tap][k][n], chunk-swizzled
// ---------------------------------------------------------------------------
__global__ void prep_w2(const float* __restrict__ w2)   // <<<9, 512>>>
{
    int t = blockIdx.x * 512 + threadIdx.x;
    if (t >= 4608) return;
    int chunk = t & 7;
    int row   = t >> 3;
    int k     = row & 31;
    int tap   = (row >> 5) % 9;
    int p     = row / 288;

    __nv_bfloat16 vals[8];
#pragma unroll
    for (int j = 0; j < 8; j++) {
        int co = chunk * 8 + j;
        float v = w2[co * 288 + k * 9 + tap];
        __nv_bfloat16 h = __float2bfloat16(v);
        vals[j] = p ? __float2bfloat16(v - __bfloat162float(h)) : h;
    }
    char* base = reinterpret_cast<char*>(g_w2bf);
    *reinterpret_cast<uint4*>(base + row * 128 + ((chunk ^ (k & 7)) << 4)) =
        *reinterpret_cast<const uint4*>(vals);
}

__global__ void prep_fcw(const float* __restrict__ fw)  // <<<98, 1024>>>
{
    int idx = blockIdx.x * 1024 + threadIdx.x;
    if (idx >= 3136 * 32) return;
    int kp = idx >> 5, d = idx & 31;
    int pos = kp >> 6, co = kp & 63;
    g_fcw[idx] = fw[d * 3136 + co * 49 + pos];
}

// ---------------------------------------------------------------------------
// Kernel 2: conv2 warp-MMA, 512 threads / 16 warps.
// Warp w: image u = w>>3, pooled row r = w&7 (r<7 active).
// Computes m-tiles {2r+1, 2r+2} x 8 n-tiles of image u. Register epilogue.
// SMEM: bias @0; A0 @1024, A1 @38144 (290x128B each); B @75264 (576x128B)
// ---------------------------------------------------------------------------
#define C2_BIAS_OFF 0
#define C2_A0_OFF   1024
#define C2_A_BYTES  (290 * 128)
#define C2_B_OFF    (C2_A0_OFF + 2 * C2_A_BYTES)     // 75264
#define C2_SMEM_BYTES (C2_B_OFF + 576 * 128)         // 148992

__global__ __launch_bounds__(512, 1)
void conv2_mma_kernel(const float* __restrict__ bias, int N)
{
    extern __shared__ __align__(16) char smem[];
    const u32 sb   = smem_to_u32(smem);
    const int tid  = threadIdx.x;
    const int w    = tid >> 5;
    const int u    = w >> 3;            // image slot 0/1
    const int r    = w & 7;             // pooled row (7 = idle)
    const u32 lane = tid & 31;
    const u32 lrow = lane & 15, lsel = lane >> 4;
    const int g    = (int)(lane >> 2);
    const int kq   = (int)(lane & 3);

    float* s_bias = reinterpret_cast<float*>(smem + C2_BIAS_OFF);
    if (tid < 64) s_bias[tid] = bias[tid];

    for (int i = tid; i < 2 * 2320; i += 512)
        reinterpret_cast<uint4*>(smem + C2_A0_OFF)[i] = make_uint4(0, 0, 0, 0);
    for (int i = tid; i < 4608; i += 512)
        reinterpret_cast<uint4*>(smem + C2_B_OFF)[i] =
            reinterpret_cast<const uint4*>(g_w2bf)[i];
    __syncthreads();

    const u32 Bbase = sb + C2_B_OFF;
    const u32 Abase = sb + C2_A0_OFF + (u32)u * C2_A_BYTES;

    for (int base = blockIdx.x * 2; base < N; base += (int)gridDim.x * 2) {
        // ---- build A interior for both images (all 512 threads) ----
#pragma unroll
        for (int v = 0; v < 2; v++) {
            int img = base + v;
            if (img >= N) break;
            const uint4* src = reinterpret_cast<const uint4*>(g_h1bf + (size_t)img * 12544);
            for (int i = tid; i < 1568; i += 512) {
                int pos = i >> 3, chunk = i & 7;
                int py = pos / 14, px = pos - py * 14;
                int row = (py + 1) * 16 + (px + 1) + 17;
                *reinterpret_cast<uint4*>(smem + C2_A0_OFF + v * C2_A_BYTES + row * 128 +
                                          ((chunk ^ (row & 7)) << 4)) = src[i];
            }
        }
        __syncthreads();

        const int img = base + u;
        if (r < 7 && img < N) {
            float C[2][8][4];
#pragma unroll
            for (int mt = 0; mt < 2; mt++)
#pragma unroll
                for (int nt = 0; nt < 8; nt++)
#pragma unroll
                    for (int q = 0; q < 4; q++) C[mt][nt][q] = 0.0f;

#pragma unroll 1
            for (int tap = 0; tap < 9; tap++) {
                const u32 rowoff = (u32)((tap / 3) * 16 + (tap % 3));
#pragma unroll
                for (int s = 0; s < 2; s++) {
                    // B-hi (shared by p0 and p1)
                    u32 bh[4][4];
#pragma unroll
                    for (int nt2 = 0; nt2 < 4; nt2++) {
                        u32 krow = (u32)(tap * 32 + s * 16) + lrow;
                        u32 bchunk = (u32)(nt2 * 2) + lsel;
                        ldsm_x4_t(bh[nt2], Bbase + krow * 128 + ((bchunk ^ (krow & 7)) << 4));
                    }
                    // A-hi
                    u32 ah[2][4];
#pragma unroll
                    for (int mt = 0; mt < 2; mt++) {
                        u32 arow = (u32)((2 * r + 1 + mt) * 16) + lrow + rowoff;
                        u32 achunk = (u32)(s * 2) + lsel;
                        ldsm_x4(ah[mt], Abase + arow * 128 + ((achunk ^ (arow & 7)) << 4));
                    }
                    // p0: Ah x Bh
#pragma unroll
                    for (int mt = 0; mt < 2; mt++)
#pragma unroll
                        for (int nt = 0; nt < 8; nt++)
                            mma_bf16(C[mt][nt], ah[mt], &bh[nt >> 1][(nt & 1) * 2]);
                    // B-lo, p2: Ah x Bl
                    {
                        u32 bl[4][4];
#pragma unroll
                        for (int nt2 = 0; nt2 < 4; nt2++) {
                            u32 krow = 288u + (u32)(tap * 32 + s * 16) + lrow;
                            u32 bchunk = (u32)(nt2 * 2) + lsel;
                            ldsm_x4_t(bl[nt2], Bbase + krow * 128 + ((bchunk ^ (krow & 7)) << 4));
                        }
#pragma unroll
                        for (int mt = 0; mt < 2; mt++)
#pragma unroll
                            for (int nt = 0; nt < 8; nt++)
                                mma_bf16(C[mt][nt], ah[mt], &bl[nt >> 1][(nt & 1) * 2]);
                    }
                    // A-lo, p1: Al x Bh
                    {
                        u32 al[2][4];
#pragma unroll
                        for (int mt = 0; mt < 2; mt++) {
                            u32 arow = (u32)((2 * r + 1 + mt) * 16) + lrow + rowoff;
                            u32 achunk = 4u + (u32)(s * 2) + lsel;
                            ldsm_x4(al[mt], Abase + arow * 128 + ((achunk ^ (arow & 7)) << 4));
                        }
#pragma unroll
                        for (int mt = 0; mt < 2; mt++)
#pragma unroll
                            for (int nt = 0; nt < 8; nt++)
                                mma_bf16(C[mt][nt], al[mt], &bh[nt >> 1][(nt & 1) * 2]);
                    }
                }
            }

            // ---- register epilogue: y-pool + x-pool via shuffles ----
            float* outb = g_h2 + (size_t)img * 3136;
#pragma unroll
            for (int nt = 0; nt < 8; nt++) {
                float p0 = fmaxf(C[0][nt][0], C[1][nt][0]);
                float p1 = fmaxf(C[0][nt][1], C[1][nt][1]);
                float p2 = fmaxf(C[0][nt][2], C[1][nt][2]);
                float p3 = fmaxf(C[0][nt][3], C[1][nt][3]);
                int srcl = (int)((lane + 4) & 31);
                float q0 = __shfl_sync(0xffffffffu, p0, srcl);
                float q1 = __shfl_sync(0xffffffffu, p1, srcl);
                float q2 = __shfl_sync(0xffffffffu, p2, srcl);
                float q3 = __shfl_sync(0xffffffffu, p3, srcl);
                float bx = s_bias[nt * 8 + 2 * kq];
                float by = s_bias[nt * 8 + 2 * kq + 1];

                if (g == 1 || g == 3 || g == 5) {
                    int pxo = (g - 1) >> 1;
                    float2 r0;
                    r0.x = fmaxf(fmaxf(p0, q0) + bx, 0.0f);
                    r0.y = fmaxf(fmaxf(p1, q1) + by, 0.0f);
                    *reinterpret_cast<float2*>(outb + (r * 7 + pxo) * 64 + nt * 8 + 2 * kq) = r0;
                    float2 r1;
                    r1.x = fmaxf(fmaxf(p2, q2) + bx, 0.0f);
                    r1.y = fmaxf(fmaxf(p3, q3) + by, 0.0f);
                    *reinterpret_cast<float2*>(outb + (r * 7 + pxo + 4) * 64 + nt * 8 + 2 * kq) = r1;
                } else if (g == 7) {
                    float2 r0;
                    r0.x = fmaxf(fmaxf(p0, q2) + bx, 0.0f);
                    r0.y = fmaxf(fmaxf(p1, q3) + by, 0.0f);
                    *reinterpret_cast<float2*>(outb + (r * 7 + 3) * 64 + nt * 8 + 2 * kq) = r0;
                }
            }
        }
        __syncthreads();
    }
}

// ---------------------------------------------------------------------------
// Kernel 3: FC  (N,3136) @ w'[3136,32] + bias -> (N,32)
// 16 images per block -> 256 blocks
// ---------------------------------------------------------------------------
#define FC_KT 112
#define FC_NB 16

__global__ __launch_bounds__(256)
void fc_kernel(const float* __restrict__ bias)
{
    __shared__ __align__(16) float a_s[FC_NB * FC_KT];
    __shared__ float b_s[FC_KT * 33];

    const int tid = threadIdx.x;
    const int n0  = blockIdx.x * FC_NB;
    const int d   = tid & 31;
    const int tr  = tid >> 5;   // 0..7, each handles 2 images

    float acc[2];
    float bv = bias[d];
    acc[0] = bv; acc[1] = bv;

    for (int kt = 0; kt < 3136; kt += FC_KT) {
        __syncthreads();
        for (int i = tid; i < FC_NB * FC_KT; i += 256) {
            int rr = i / FC_KT, c = i - rr * FC_KT;
            a_s[rr * FC_KT + c] = g_h2[(size_t)(n0 + rr) * 3136 + kt + c];
        }
        for (int i = tid; i < 32 * FC_KT; i += 256) {
            int c = i >> 5, dd = i & 31;
            b_s[c * 33 + dd] = g_fcw[(size_t)(kt + c) * 32 + dd];
        }
        __syncthreads();

#pragma unroll 4
        for (int kk = 0; kk < FC_KT; kk += 4) {
            float w0 = b_s[(kk + 0) * 33 + d];
            float w1 = b_s[(kk + 1) * 33 + d];
            float w2 = b_s[(kk + 2) * 33 + d];
            float w3 = b_s[(kk + 3) * 33 + d];
#pragma unroll
            for (int i = 0; i < 2; i++) {
                float4 av = *reinterpret_cast<const float4*>(
                    a_s + (tr * 2 + i) * FC_KT + kk);
                acc[i] = fmaf(av.x, w0, acc[i]);
                acc[i] = fmaf(av.y, w1, acc[i]);
                acc[i] = fmaf(av.z, w2, acc[i]);
                acc[i] = fmaf(av.w, w3, acc[i]);
            }
        }
    }

#pragma unroll
    for (int i = 0; i < 2; i++)
        g_fc[(size_t)(n0 + tr * 2 + i) * 32 + d] = acc[i];
}

// ---------------------------------------------------------------------------
// Kernel 4: hyperbolic MLR  (N,32) -> (N,10), c = 1
// ---------------------------------------------------------------------------
__global__ __launch_bounds__(256)
void mlr_kernel(const float* __restrict__ hw,
                const float* __restrict__ hb,
                float* __restrict__ out, int total)
{
    int i = blockIdx.x * blockDim.x + threadIdx.x;
    if (i >= total) return;
    int n = i / 10;
    int k = i - n * 10;

    const float* xv = g_fc + (size_t)n * 32;
    const float* wv = hw + k * 32;
    const float* bv = hb + k * 32;

    float x2 = 0.f, b2 = 0.f, w2 = 0.f, xb = 0.f, xw = 0.f, wb = 0.f;
#pragma unroll
    for (int j = 0; j < 32; j++) {
        float xj = xv[j], wj = wv[j], bj = bv[j];
        x2 += xj * xj;  b2 += bj * bj;  w2 += wj * wj;
        xb += xj * bj;  xw += xj * wj;  wb += wj * bj;
    }

    const float EPSf = 1e-5f;
    const float MN   = 0.99999f;

    float inner  = -xb;
    float w_norm = sqrtf(w2);
    float inv_wn = 1.0f / fmaxf(w_norm, 1e-12f);
    float wb_n   = -wb * inv_wn;
    float xw_n   = xw * inv_wn;

    float a_num = 1.0f + 2.0f * inner + x2;
    float b_num = 1.0f - b2;
    float denom = 1.0f + 2.0f * inner + x2 * b2;
    float alpha = a_num / fmaxf(denom, EPSf);
    float beta  = b_num / denom;
    float mob2  = alpha * alpha * b2 + 2.0f * alpha * beta * inner
                + beta * beta * x2;
    float sq    = sqrtf(mob2);
    float normalizer = (sq > MN) ? (MN / fmaxf(sq, EPSf)) : 1.0f;
    float mob2f = (sq < MN) ? mob2 : (MN * MN);
    float hyp   = (alpha * wb_n + beta * xw_n) * normalizer;
    float asin_in = 2.0f * hyp / fmaxf(1.0f - mob2f, EPSf);

    out[i] = (2.0f / fmaxf(1.0f - b2, EPSf)) * w_norm * asinhf(asin_in);
}

// ---------------------------------------------------------------------------
// Launch
// ---------------------------------------------------------------------------
extern "C" void kernel_launch(void* const* d_in, const int* in_sizes, int n_in,
                              void* d_out, int out_size) {
    const float* x   = (const float*)d_in[0];
    const float* w1  = (const float*)d_in[1];
    const float* b1  = (const float*)d_in[2];
    const float* w2  = (const float*)d_in[3];
    const float* b2  = (const float*)d_in[4];
    const float* fw  = (const float*)d_in[5];
    const float* fb  = (const float*)d_in[6];
    const float* hw  = (const float*)d_in[7];
    const float* hb  = (const float*)d_in[8];
    float* out = (float*)d_out;

    const int N = in_sizes[0] / 784;

    cudaFuncSetAttribute(conv2_mma_kernel,
                         cudaFuncAttributeMaxDynamicSharedMemorySize,
                         C2_SMEM_BYTES);

    prep_w2<<<9, 512>>>(w2);
    prep_fcw<<<98, 1024>>>(fw);
    conv1_kernel<<<N, 256>>>(x, w1, b1);
    int pairs = (N + 1) / 2;
    int g2 = pairs < 148 ? pairs : 148;
    conv2_mma_kernel<<<g2, 512, C2_SMEM_BYTES>>>(b2, N);
    fc_kernel<<<N / FC_NB, 256>>>(fb);
    int total = N * 10;
    mlr_kernel<<<(total + 255) / 256, 256>>>(hw, hb, out, total);
}

// round 11
// speedup vs baseline: 1.8677x; 1.0078x over previous
#include <cuda_runtime.h>
#include <cuda_bf16.h>
#include <math.h>

typedef unsigned long long u64;
typedef unsigned int u32;

// ---------------------------------------------------------------------------
// Scratch (allocation-free: __device__ globals)
// ---------------------------------------------------------------------------
#define MAXN 4096
__device__ __align__(16) __nv_bfloat16 g_h1bf[MAXN * 196 * 64]; // conv1 out [n][pos196][hi32|lo32]
__device__ __align__(16) float g_h2[MAXN * 3136];               // conv2 out [n][pos49*64+co]
__device__ __align__(16) float g_fc[MAXN * 32];                 // FC out (N,32)
__device__ __align__(16) float g_fcw[3136 * 32];                // fc_w transposed [pos*64+co][d]
__device__ __align__(16) __nv_bfloat16 g_w2bf[2 * 9 * 32 * 64]; // conv2 w, swizzled

// ---------------------------------------------------------------------------
// Warp-MMA helpers
// ---------------------------------------------------------------------------
__device__ __forceinline__ u32 smem_to_u32(const void* p) {
    u32 a;
    asm("{ .reg .u64 t; cvta.to.shared.u64 t, %1; cvt.u32.u64 %0, t; }"
        : "=r"(a) : "l"(p));
    return a;
}
__device__ __forceinline__ void ldsm_x4(u32* r, u32 addr) {
    asm volatile("ldmatrix.sync.aligned.m8n8.x4.shared.b16 {%0,%1,%2,%3}, [%4];"
        : "=r"(r[0]), "=r"(r[1]), "=r"(r[2]), "=r"(r[3]) : "r"(addr));
}
__device__ __forceinline__ void ldsm_x4_t(u32* r, u32 addr) {
    asm volatile("ldmatrix.sync.aligned.m8n8.x4.trans.shared.b16 {%0,%1,%2,%3}, [%4];"
        : "=r"(r[0]), "=r"(r[1]), "=r"(r[2]), "=r"(r[3]) : "r"(addr));
}
__device__ __forceinline__ void mma_bf16(float* c, const u32* a, const u32* b) {
    asm volatile(
        "mma.sync.aligned.m16n8k16.row.col.f32.bf16.bf16.f32 "
        "{%0,%1,%2,%3}, {%4,%5,%6,%7}, {%8,%9}, {%0,%1,%2,%3};"
        : "+f"(c[0]), "+f"(c[1]), "+f"(c[2]), "+f"(c[3])
        : "r"(a[0]), "r"(a[1]), "r"(a[2]), "r"(a[3]), "r"(b[0]), "r"(b[1]));
}

// ---------------------------------------------------------------------------
// Kernel 1: conv1 (1->32, 3x3, pad 1) + relu + maxpool2 -> bf16 hi/lo
// ---------------------------------------------------------------------------
__global__ __launch_bounds__(256)
void conv1_kernel(const float* __restrict__ x,
                  const float* __restrict__ w,
                  const float* __restrict__ bias)
{
    __shared__ __align__(16) float s_in[30 * 30];
    __shared__ __align__(16) float s_w[9 * 32];
    __shared__ float s_b[32];

    const int n   = blockIdx.x;
    const int tid = threadIdx.x;

    for (int i = tid; i < 900; i += 256) s_in[i] = 0.0f;
    for (int i = tid; i < 288; i += 256) {
        int co = i / 9, k = i % 9;
        s_w[k * 32 + co] = w[co * 9 + k];
    }
    if (tid < 32) s_b[tid] = bias[tid];
    __syncthreads();

    const float* xb = x + (size_t)n * 784;
    for (int i = tid; i < 784; i += 256) {
        int y = i / 28, c = i % 28;
        s_in[(y + 1) * 30 + (c + 1)] = xb[i];
    }
    __syncthreads();

    const float2* s_w2 = reinterpret_cast<const float2*>(s_w);
    __nv_bfloat162* ob = reinterpret_cast<__nv_bfloat162*>(g_h1bf) + (size_t)n * 6272;

    for (int it = tid; it < 3136; it += 256) {
        const int pair = it & 15;
        const int pos  = it >> 4;
        const int py   = pos / 14;
        const int px   = pos - py * 14;

        float pv[4][4];
#pragma unroll
        for (int r = 0; r < 4; r++)
#pragma unroll
            for (int c = 0; c < 4; c++)
                pv[r][c] = s_in[(2 * py + r) * 30 + (2 * px + c)];

        float2 bb = make_float2(s_b[pair * 2], s_b[pair * 2 + 1]);
        float a0x = bb.x, a0y = bb.y, a1x = bb.x, a1y = bb.y;
        float a2x = bb.x, a2y = bb.y, a3x = bb.x, a3y = bb.y;

#pragma unroll
        for (int ky = 0; ky < 3; ky++)
#pragma unroll
            for (int kx = 0; kx < 3; kx++) {
                float2 wf = s_w2[(ky * 3 + kx) * 16 + pair];
                float p00 = pv[ky][kx],     p01 = pv[ky][kx + 1];
                float p10 = pv[ky + 1][kx], p11 = pv[ky + 1][kx + 1];
                a0x = fmaf(p00, wf.x, a0x); a0y = fmaf(p00, wf.y, a0y);
                a1x = fmaf(p01, wf.x, a1x); a1y = fmaf(p01, wf.y, a1y);
                a2x = fmaf(p10, wf.x, a2x); a2y = fmaf(p10, wf.y, a2y);
                a3x = fmaf(p11, wf.x, a3x); a3y = fmaf(p11, wf.y, a3y);
            }

        float mlo = fmaxf(fmaxf(fmaxf(a0x, a1x), fmaxf(a2x, a3x)), 0.0f);
        float mhi = fmaxf(fmaxf(fmaxf(a0y, a1y), fmaxf(a2y, a3y)), 0.0f);

        __nv_bfloat16 hx = __float2bfloat16(mlo);
        __nv_bfloat16 hy = __float2bfloat16(mhi);
        __nv_bfloat16 lx = __float2bfloat16(mlo - __bfloat162float(hx));
        __nv_bfloat16 ly = __float2bfloat16(mhi - __bfloat162float(hy));
        __nv_bfloat162 hv; hv.x = hx; hv.y = hy;
        __nv_bfloat162 lv; lv.x = lx; lv.y = ly;
        ob[pos * 32 + pair]      = hv;
        ob[pos * 32 + 16 + pair] = lv;
    }
}

// ---------------------------------------------------------------------------
// Prep: conv2 weights -> bf16 hi/lo, [split][tap][k][n], chunk-swizzled
// ---------------------------------------------------------------------------
__global__ void prep_w2(const float* __restrict__ w2)   // <<<9, 512>>>
{
    int t = blockIdx.x * 512 + threadIdx.x;
    if (t >= 4608) return;
    int chunk = t & 7;
    int row   = t >> 3;
    int k     = row & 31;
    int tap   = (row >> 5) % 9;
    int p     = row / 288;

    __nv_bfloat16 vals[8];
#pragma unroll
    for (int j = 0; j < 8; j++) {
        int co = chunk * 8 + j;
        float v = w2[co * 288 + k * 9 + tap];
        __nv_bfloat16 h = __float2bfloat16(v);
        vals[j] = p ? __float2bfloat16(v - __bfloat162float(h)) : h;
    }
    char* base = reinterpret_cast<char*>(g_w2bf);
    *reinterpret_cast<uint4*>(base + row * 128 + ((chunk ^ (k & 7)) << 4)) =
        *reinterpret_cast<const uint4*>(vals);
}

__global__ void prep_fcw(const float* __restrict__ fw)  // <<<98, 1024>>>
{
    int idx = blockIdx.x * 1024 + threadIdx.x;
    if (idx >= 3136 * 32) return;
    int kp = idx >> 5, d = idx & 31;
    int pos = kp >> 6, co = kp & 63;
    g_fcw[idx] = fw[d * 3136 + co * 49 + pos];
}

// ---------------------------------------------------------------------------
// Kernel 2: conv2 warp-MMA. 1 image/CTA, 256 threads, 2 CTAs/SM
// (smem 109KB each) so independent CTAs keep the tensor pipe fed while the
// other builds A / syncs. Warp r (0..6) = pooled row; m-tiles {2r+1, 2r+2}.
// SMEM: bias @0; A @1024 (290x128B); B @38144 (576x128B). Total 111872 B.
// ---------------------------------------------------------------------------
#define C2_BIAS_OFF 0
#define C2_A_OFF    1024
#define C2_B_OFF    (1024 + 290 * 128)            // 38144
#define C2_SMEM_BYTES (C2_B_OFF + 576 * 128)      // 111872

__global__ __launch_bounds__(256, 2)
void conv2_mma_kernel(const float* __restrict__ bias, int N)
{
    extern __shared__ __align__(16) char smem[];
    const u32 sb   = smem_to_u32(smem);
    const int tid  = threadIdx.x;
    const int r    = tid >> 5;          // warp = pooled row (7 = helper/idle)
    const u32 lane = tid & 31;
    const u32 lrow = lane & 15, lsel = lane >> 4;
    const int g    = (int)(lane >> 2);
    const int kq   = (int)(lane & 3);

    float* s_bias = reinterpret_cast<float*>(smem + C2_BIAS_OFF);
    if (tid < 64) s_bias[tid] = bias[tid];

    for (int i = tid; i < 2320; i += 256)
        reinterpret_cast<uint4*>(smem + C2_A_OFF)[i] = make_uint4(0, 0, 0, 0);
    for (int i = tid; i < 4608; i += 256)
        reinterpret_cast<uint4*>(smem + C2_B_OFF)[i] =
            reinterpret_cast<const uint4*>(g_w2bf)[i];
    __syncthreads();

    const u32 Bbase = sb + C2_B_OFF;
    const u32 Abase = sb + C2_A_OFF;

    for (int img = blockIdx.x; img < N; img += (int)gridDim.x) {
        // ---- build A interior (all 256 threads) ----
        const uint4* src = reinterpret_cast<const uint4*>(g_h1bf + (size_t)img * 12544);
        for (int i = tid; i < 1568; i += 256) {
            int pos = i >> 3, chunk = i & 7;
            int py = pos / 14, px = pos - py * 14;
            int row = (py + 1) * 16 + (px + 1) + 17;
            *reinterpret_cast<uint4*>(smem + C2_A_OFF + row * 128 +
                                      ((chunk ^ (row & 7)) << 4)) = src[i];
        }
        __syncthreads();

        if (r < 7) {
            float C[2][8][4];
#pragma unroll
            for (int mt = 0; mt < 2; mt++)
#pragma unroll
                for (int nt = 0; nt < 8; nt++)
#pragma unroll
                    for (int q = 0; q < 4; q++) C[mt][nt][q] = 0.0f;

#pragma unroll 1
            for (int tap = 0; tap < 9; tap++) {
                const u32 rowoff = (u32)((tap / 3) * 16 + (tap % 3));
#pragma unroll
                for (int s = 0; s < 2; s++) {
                    // B-hi (shared by p0 and p1)
                    u32 bh[4][4];
#pragma unroll
                    for (int nt2 = 0; nt2 < 4; nt2++) {
                        u32 krow = (u32)(tap * 32 + s * 16) + lrow;
                        u32 bchunk = (u32)(nt2 * 2) + lsel;
                        ldsm_x4_t(bh[nt2], Bbase + krow * 128 + ((bchunk ^ (krow & 7)) << 4));
                    }
                    // A-hi
                    u32 ah[2][4];
#pragma unroll
                    for (int mt = 0; mt < 2; mt++) {
                        u32 arow = (u32)((2 * r + 1 + mt) * 16) + lrow + rowoff;
                        u32 achunk = (u32)(s * 2) + lsel;
                        ldsm_x4(ah[mt], Abase + arow * 128 + ((achunk ^ (arow & 7)) << 4));
                    }
                    // p0: Ah x Bh
#pragma unroll
                    for (int mt = 0; mt < 2; mt++)
#pragma unroll
                        for (int nt = 0; nt < 8; nt++)
                            mma_bf16(C[mt][nt], ah[mt], &bh[nt >> 1][(nt & 1) * 2]);
                    // B-lo, p2: Ah x Bl
                    {
                        u32 bl[4][4];
#pragma unroll
                        for (int nt2 = 0; nt2 < 4; nt2++) {
                            u32 krow = 288u + (u32)(tap * 32 + s * 16) + lrow;
                            u32 bchunk = (u32)(nt2 * 2) + lsel;
                            ldsm_x4_t(bl[nt2], Bbase + krow * 128 + ((bchunk ^ (krow & 7)) << 4));
                        }
#pragma unroll
                        for (int mt = 0; mt < 2; mt++)
#pragma unroll
                            for (int nt = 0; nt < 8; nt++)
                                mma_bf16(C[mt][nt], ah[mt], &bl[nt >> 1][(nt & 1) * 2]);
                    }
                    // A-lo, p1: Al x Bh
                    {
                        u32 al[2][4];
#pragma unroll
                        for (int mt = 0; mt < 2; mt++) {
                            u32 arow = (u32)((2 * r + 1 + mt) * 16) + lrow + rowoff;
                            u32 achunk = 4u + (u32)(s * 2) + lsel;
                            ldsm_x4(al[mt], Abase + arow * 128 + ((achunk ^ (arow & 7)) << 4));
                        }
#pragma unroll
                        for (int mt = 0; mt < 2; mt++)
#pragma unroll
                            for (int nt = 0; nt < 8; nt++)
                                mma_bf16(C[mt][nt], al[mt], &bh[nt >> 1][(nt & 1) * 2]);
                    }
                }
            }

            // ---- register epilogue: y-pool + x-pool via shuffles ----
            float* outb = g_h2 + (size_t)img * 3136;
#pragma unroll
            for (int nt = 0; nt < 8; nt++) {
                float p0 = fmaxf(C[0][nt][0], C[1][nt][0]);
                float p1 = fmaxf(C[0][nt][1], C[1][nt][1]);
                float p2 = fmaxf(C[0][nt][2], C[1][nt][2]);
                float p3 = fmaxf(C[0][nt][3], C[1][nt][3]);
                int srcl = (int)((lane + 4) & 31);
                float q0 = __shfl_sync(0xffffffffu, p0, srcl);
                float q1 = __shfl_sync(0xffffffffu, p1, srcl);
                float q2 = __shfl_sync(0xffffffffu, p2, srcl);
                float q3 = __shfl_sync(0xffffffffu, p3, srcl);
                float bx = s_bias[nt * 8 + 2 * kq];
                float by = s_bias[nt * 8 + 2 * kq + 1];

                if (g == 1 || g == 3 || g == 5) {
                    int pxo = (g - 1) >> 1;
                    float2 r0;
                    r0.x = fmaxf(fmaxf(p0, q0) + bx, 0.0f);
                    r0.y = fmaxf(fmaxf(p1, q1) + by, 0.0f);
                    *reinterpret_cast<float2*>(outb + (r * 7 + pxo) * 64 + nt * 8 + 2 * kq) = r0;
                    float2 r1;
                    r1.x = fmaxf(fmaxf(p2, q2) + bx, 0.0f);
                    r1.y = fmaxf(fmaxf(p3, q3) + by, 0.0f);
                    *reinterpret_cast<float2*>(outb + (r * 7 + pxo + 4) * 64 + nt * 8 + 2 * kq) = r1;
                } else if (g == 7) {
                    float2 r0;
                    r0.x = fmaxf(fmaxf(p0, q2) + bx, 0.0f);
                    r0.y = fmaxf(fmaxf(p1, q3) + by, 0.0f);
                    *reinterpret_cast<float2*>(outb + (r * 7 + 3) * 64 + nt * 8 + 2 * kq) = r0;
                }
            }
        }
        __syncthreads();
    }
}

// ---------------------------------------------------------------------------
// Kernel 3: FC  (N,3136) @ w'[3136,32] + bias -> (N,32)
// ---------------------------------------------------------------------------
#define FC_KT 112
#define FC_NB 16

__global__ __launch_bounds__(256)
void fc_kernel(const float* __restrict__ bias)
{
    __shared__ __align__(16) float a_s[FC_NB * FC_KT];
    __shared__ float b_s[FC_KT * 33];

    const int tid = threadIdx.x;
    const int n0  = blockIdx.x * FC_NB;
    const int d   = tid & 31;
    const int tr  = tid >> 5;

    float acc[2];
    float bv = bias[d];
    acc[0] = bv; acc[1] = bv;

    for (int kt = 0; kt < 3136; kt += FC_KT) {
        __syncthreads();
        for (int i = tid; i < FC_NB * FC_KT; i += 256) {
            int rr = i / FC_KT, c = i - rr * FC_KT;
            a_s[rr * FC_KT + c] = g_h2[(size_t)(n0 + rr) * 3136 + kt + c];
        }
        for (int i = tid; i < 32 * FC_KT; i += 256) {
            int c = i >> 5, dd = i & 31;
            b_s[c * 33 + dd] = g_fcw[(size_t)(kt + c) * 32 + dd];
        }
        __syncthreads();

#pragma unroll 4
        for (int kk = 0; kk < FC_KT; kk += 4) {
            float w0 = b_s[(kk + 0) * 33 + d];
            float w1 = b_s[(kk + 1) * 33 + d];
            float w2 = b_s[(kk + 2) * 33 + d];
            float w3 = b_s[(kk + 3) * 33 + d];
#pragma unroll
            for (int i = 0; i < 2; i++) {
                float4 av = *reinterpret_cast<const float4*>(
                    a_s + (tr * 2 + i) * FC_KT + kk);
                acc[i] = fmaf(av.x, w0, acc[i]);
                acc[i] = fmaf(av.y, w1, acc[i]);
                acc[i] = fmaf(av.z, w2, acc[i]);
                acc[i] = fmaf(av.w, w3, acc[i]);
            }
        }
    }

#pragma unroll
    for (int i = 0; i < 2; i++)
        g_fc[(size_t)(n0 + tr * 2 + i) * 32 + d] = acc[i];
}

// ---------------------------------------------------------------------------
// Kernel 4: hyperbolic MLR  (N,32) -> (N,10), c = 1
// ---------------------------------------------------------------------------
__global__ __launch_bounds__(256)
void mlr_kernel(const float* __restrict__ hw,
                const float* __restrict__ hb,
                float* __restrict__ out, int total)
{
    int i = blockIdx.x * blockDim.x + threadIdx.x;
    if (i >= total) return;
    int n = i / 10;
    int k = i - n * 10;

    const float* xv = g_fc + (size_t)n * 32;
    const float* wv = hw + k * 32;
    const float* bv = hb + k * 32;

    float x2 = 0.f, b2 = 0.f, w2 = 0.f, xb = 0.f, xw = 0.f, wb = 0.f;
#pragma unroll
    for (int j = 0; j < 32; j++) {
        float xj = xv[j], wj = wv[j], bj = bv[j];
        x2 += xj * xj;  b2 += bj * bj;  w2 += wj * wj;
        xb += xj * bj;  xw += xj * wj;  wb += wj * bj;
    }

    const float EPSf = 1e-5f;
    const float MN   = 0.99999f;

    float inner  = -xb;
    float w_norm = sqrtf(w2);
    float inv_wn = 1.0f / fmaxf(w_norm, 1e-12f);
    float wb_n   = -wb * inv_wn;
    float xw_n   = xw * inv_wn;

    float a_num = 1.0f + 2.0f * inner + x2;
    float b_num = 1.0f - b2;
    float denom = 1.0f + 2.0f * inner + x2 * b2;
    float alpha = a_num / fmaxf(denom, EPSf);
    float beta  = b_num / denom;
    float mob2  = alpha * alpha * b2 + 2.0f * alpha * beta * inner
                + beta * beta * x2;
    float sq    = sqrtf(mob2);
    float normalizer = (sq > MN) ? (MN / fmaxf(sq, EPSf)) : 1.0f;
    float mob2f = (sq < MN) ? mob2 : (MN * MN);
    float hyp   = (alpha * wb_n + beta * xw_n) * normalizer;
    float asin_in = 2.0f * hyp / fmaxf(1.0f - mob2f, EPSf);

    out[i] = (2.0f / fmaxf(1.0f - b2, EPSf)) * w_norm * asinhf(asin_in);
}

// ---------------------------------------------------------------------------
// Launch
// ---------------------------------------------------------------------------
extern "C" void kernel_launch(void* const* d_in, const int* in_sizes, int n_in,
                              void* d_out, int out_size) {
    const float* x   = (const float*)d_in[0];
    const float* w1  = (const float*)d_in[1];
    const float* b1  = (const float*)d_in[2];
    const float* w2  = (const float*)d_in[3];
    const float* b2  = (const float*)d_in[4];
    const float* fw  = (const float*)d_in[5];
    const float* fb  = (const float*)d_in[6];
    const float* hw  = (const float*)d_in[7];
    const float* hb  = (const float*)d_in[8];
    float* out = (float*)d_out;

    const int N = in_sizes[0] / 784;

    cudaFuncSetAttribute(conv2_mma_kernel,
                         cudaFuncAttributeMaxDynamicSharedMemorySize,
                         C2_SMEM_BYTES);

    prep_w2<<<9, 512>>>(w2);
    prep_fcw<<<98, 1024>>>(fw);
    conv1_kernel<<<N, 256>>>(x, w1, b1);
    int g2 = N < 296 ? N : 296;
    conv2_mma_kernel<<<g2, 256, C2_SMEM_BYTES>>>(b2, N);
    fc_kernel<<<N / FC_NB, 256>>>(fb);
    int total = N * 10;
    mlr_kernel<<<(total + 255) / 256, 256>>>(hw, hb, out, total);
}

// round 12
// speedup vs baseline: 1.8812x; 1.0073x over previous
#include <cuda_runtime.h>
#include <cuda_bf16.h>
#include <math.h>

typedef unsigned long long u64;
typedef unsigned int u32;

// ---------------------------------------------------------------------------
// Scratch (allocation-free: __device__ globals)
// ---------------------------------------------------------------------------
#define MAXN 4096
__device__ __align__(16) __nv_bfloat16 g_h1bf[MAXN * 196 * 64]; // conv1 out [n][pos196][hi32|lo32]
__device__ __align__(16) float g_h2[MAXN * 3136];               // conv2 out [n][pos49*64+co]
__device__ __align__(16) float g_fc[MAXN * 32];                 // FC out (N,32)
__device__ __align__(16) float g_fcw[3136 * 32];                // fc_w transposed [pos*64+co][d]
__device__ __align__(16) __nv_bfloat16 g_w2bf[2 * 9 * 32 * 64]; // conv2 w, swizzled

// ---------------------------------------------------------------------------
// Warp-MMA helpers
// ---------------------------------------------------------------------------
__device__ __forceinline__ u32 smem_to_u32(const void* p) {
    u32 a;
    asm("{ .reg .u64 t; cvta.to.shared.u64 t, %1; cvt.u32.u64 %0, t; }"
        : "=r"(a) : "l"(p));
    return a;
}
__device__ __forceinline__ void ldsm_x4(u32* r, u32 addr) {
    asm volatile("ldmatrix.sync.aligned.m8n8.x4.shared.b16 {%0,%1,%2,%3}, [%4];"
        : "=r"(r[0]), "=r"(r[1]), "=r"(r[2]), "=r"(r[3]) : "r"(addr));
}
__device__ __forceinline__ void ldsm_x4_t(u32* r, u32 addr) {
    asm volatile("ldmatrix.sync.aligned.m8n8.x4.trans.shared.b16 {%0,%1,%2,%3}, [%4];"
        : "=r"(r[0]), "=r"(r[1]), "=r"(r[2]), "=r"(r[3]) : "r"(addr));
}
__device__ __forceinline__ void mma_bf16(float* c, const u32* a, const u32* b) {
    asm volatile(
        "mma.sync.aligned.m16n8k16.row.col.f32.bf16.bf16.f32 "
        "{%0,%1,%2,%3}, {%4,%5,%6,%7}, {%8,%9}, {%0,%1,%2,%3};"
        : "+f"(c[0]), "+f"(c[1]), "+f"(c[2]), "+f"(c[3])
        : "r"(a[0]), "r"(a[1]), "r"(a[2]), "r"(a[3]), "r"(b[0]), "r"(b[1]));
}

// ---------------------------------------------------------------------------
// Kernel 1: conv1 (1->32, 3x3, pad 1) + relu + maxpool2 -> bf16 hi/lo
// ---------------------------------------------------------------------------
__global__ __launch_bounds__(256)
void conv1_kernel(const float* __restrict__ x,
                  const float* __restrict__ w,
                  const float* __restrict__ bias)
{
    __shared__ __align__(16) float s_in[30 * 30];
    __shared__ __align__(16) float s_w[9 * 32];
    __shared__ float s_b[32];

    const int n   = blockIdx.x;
    const int tid = threadIdx.x;

    for (int i = tid; i < 900; i += 256) s_in[i] = 0.0f;
    for (int i = tid; i < 288; i += 256) {
        int co = i / 9, k = i % 9;
        s_w[k * 32 + co] = w[co * 9 + k];
    }
    if (tid < 32) s_b[tid] = bias[tid];
    __syncthreads();

    const float* xb = x + (size_t)n * 784;
    for (int i = tid; i < 784; i += 256) {
        int y = i / 28, c = i % 28;
        s_in[(y + 1) * 30 + (c + 1)] = xb[i];
    }
    __syncthreads();

    const float2* s_w2 = reinterpret_cast<const float2*>(s_w);
    __nv_bfloat162* ob = reinterpret_cast<__nv_bfloat162*>(g_h1bf) + (size_t)n * 6272;

    for (int it = tid; it < 3136; it += 256) {
        const int pair = it & 15;
        const int pos  = it >> 4;
        const int py   = pos / 14;
        const int px   = pos - py * 14;

        float pv[4][4];
#pragma unroll
        for (int r = 0; r < 4; r++)
#pragma unroll
            for (int c = 0; c < 4; c++)
                pv[r][c] = s_in[(2 * py + r) * 30 + (2 * px + c)];

        float2 bb = make_float2(s_b[pair * 2], s_b[pair * 2 + 1]);
        float a0x = bb.x, a0y = bb.y, a1x = bb.x, a1y = bb.y;
        float a2x = bb.x, a2y = bb.y, a3x = bb.x, a3y = bb.y;

#pragma unroll
        for (int ky = 0; ky < 3; ky++)
#pragma unroll
            for (int kx = 0; kx < 3; kx++) {
                float2 wf = s_w2[(ky * 3 + kx) * 16 + pair];
                float p00 = pv[ky][kx],     p01 = pv[ky][kx + 1];
                float p10 = pv[ky + 1][kx], p11 = pv[ky + 1][kx + 1];
                a0x = fmaf(p00, wf.x, a0x); a0y = fmaf(p00, wf.y, a0y);
                a1x = fmaf(p01, wf.x, a1x); a1y = fmaf(p01, wf.y, a1y);
                a2x = fmaf(p10, wf.x, a2x); a2y = fmaf(p10, wf.y, a2y);
                a3x = fmaf(p11, wf.x, a3x); a3y = fmaf(p11, wf.y, a3y);
            }

        float mlo = fmaxf(fmaxf(fmaxf(a0x, a1x), fmaxf(a2x, a3x)), 0.0f);
        float mhi = fmaxf(fmaxf(fmaxf(a0y, a1y), fmaxf(a2y, a3y)), 0.0f);

        __nv_bfloat16 hx = __float2bfloat16(mlo);
        __nv_bfloat16 hy = __float2bfloat16(mhi);
        __nv_bfloat16 lx = __float2bfloat16(mlo - __bfloat162float(hx));
        __nv_bfloat16 ly = __float2bfloat16(mhi - __bfloat162float(hy));
        __nv_bfloat162 hv; hv.x = hx; hv.y = hy;
        __nv_bfloat162 lv; lv.x = lx; lv.y = ly;
        ob[pos * 32 + pair]      = hv;
        ob[pos * 32 + 16 + pair] = lv;
    }
}

// ---------------------------------------------------------------------------
// Prep: conv2 weights -> bf16 hi/lo, [split][tap][k][n], chunk-swizzled
// ---------------------------------------------------------------------------
__global__ void prep_w2(const float* __restrict__ w2)   // <<<9, 512>>>
{
    int t = blockIdx.x * 512 + threadIdx.x;
    if (t >= 4608) return;
    int chunk = t & 7;
    int row   = t >> 3;
    int k     = row & 31;
    int tap   = (row >> 5) % 9;
    int p     = row / 288;

    __nv_bfloat16 vals[8];
#pragma unroll
    for (int j = 0; j < 8; j++) {
        int co = chunk * 8 + j;
        float v = w2[co * 288 + k * 9 + tap];
        __nv_bfloat16 h = __float2bfloat16(v);
        vals[j] = p ? __float2bfloat16(v - __bfloat162float(h)) : h;
    }
    char* base = reinterpret_cast<char*>(g_w2bf);
    *reinterpret_cast<uint4*>(base + row * 128 + ((chunk ^ (k & 7)) << 4)) =
        *reinterpret_cast<const uint4*>(vals);
}

__global__ void prep_fcw(const float* __restrict__ fw)  // <<<98, 1024>>>
{
    int idx = blockIdx.x * 1024 + threadIdx.x;
    if (idx >= 3136 * 32) return;
    int kp = idx >> 5, d = idx & 31;
    int pos = kp >> 6, co = kp & 63;
    g_fcw[idx] = fw[d * 3136 + co * 49 + pos];
}

// ---------------------------------------------------------------------------
// Kernel 2: conv2 warp-MMA. 1 image/CTA, 256 threads, 2 CTAs/SM.
// Per (tap,s): ALL 12 LDSM issued up front, then 48 HMMA — one latency
// window per 48 HMMA instead of three per 16.
// SMEM: bias @0; A @1024 (290x128B); B @38144 (576x128B). Total 111872 B.
// ---------------------------------------------------------------------------
#define C2_BIAS_OFF 0
#define C2_A_OFF    1024
#define C2_B_OFF    (1024 + 290 * 128)            // 38144
#define C2_SMEM_BYTES (C2_B_OFF + 576 * 128)      // 111872

__global__ __launch_bounds__(256, 2)
void conv2_mma_kernel(const float* __restrict__ bias, int N)
{
    extern __shared__ __align__(16) char smem[];
    const u32 sb   = smem_to_u32(smem);
    const int tid  = threadIdx.x;
    const int r    = tid >> 5;          // warp = pooled row (7 = helper/idle)
    const u32 lane = tid & 31;
    const u32 lrow = lane & 15, lsel = lane >> 4;
    const int g    = (int)(lane >> 2);
    const int kq   = (int)(lane & 3);

    float* s_bias = reinterpret_cast<float*>(smem + C2_BIAS_OFF);
    if (tid < 64) s_bias[tid] = bias[tid];

    for (int i = tid; i < 2320; i += 256)
        reinterpret_cast<uint4*>(smem + C2_A_OFF)[i] = make_uint4(0, 0, 0, 0);
    for (int i = tid; i < 4608; i += 256)
        reinterpret_cast<uint4*>(smem + C2_B_OFF)[i] =
            reinterpret_cast<const uint4*>(g_w2bf)[i];
    __syncthreads();

    const u32 Bbase = sb + C2_B_OFF;
    const u32 Abase = sb + C2_A_OFF;

    for (int img = blockIdx.x; img < N; img += (int)gridDim.x) {
        // ---- build A interior (all 256 threads) ----
        const uint4* src = reinterpret_cast<const uint4*>(g_h1bf + (size_t)img * 12544);
        for (int i = tid; i < 1568; i += 256) {
            int pos = i >> 3, chunk = i & 7;
            int py = pos / 14, px = pos - py * 14;
            int row = (py + 1) * 16 + (px + 1) + 17;
            *reinterpret_cast<uint4*>(smem + C2_A_OFF + row * 128 +
                                      ((chunk ^ (row & 7)) << 4)) = src[i];
        }
        __syncthreads();

        if (r < 7) {
            float C[2][8][4];
#pragma unroll
            for (int mt = 0; mt < 2; mt++)
#pragma unroll
                for (int nt = 0; nt < 8; nt++)
#pragma unroll
                    for (int q = 0; q < 4; q++) C[mt][nt][q] = 0.0f;

#pragma unroll 1
            for (int tap = 0; tap < 9; tap++) {
                const u32 rowoff = (u32)((tap / 3) * 16 + (tap % 3));
#pragma unroll
                for (int s = 0; s < 2; s++) {
                    // ---- front-load ALL fragments for this (tap,s) ----
                    u32 bh[4][4], bl[4][4], ah[2][4], al[2][4];
#pragma unroll
                    for (int nt2 = 0; nt2 < 4; nt2++) {
                        u32 krow = (u32)(tap * 32 + s * 16) + lrow;
                        u32 bchunk = (u32)(nt2 * 2) + lsel;
                        ldsm_x4_t(bh[nt2], Bbase + krow * 128 + ((bchunk ^ (krow & 7)) << 4));
                    }
#pragma unroll
                    for (int mt = 0; mt < 2; mt++) {
                        u32 arow = (u32)((2 * r + 1 + mt) * 16) + lrow + rowoff;
                        u32 achunk = (u32)(s * 2) + lsel;
                        ldsm_x4(ah[mt], Abase + arow * 128 + ((achunk ^ (arow & 7)) << 4));
                    }
#pragma unroll
                    for (int nt2 = 0; nt2 < 4; nt2++) {
                        u32 krow = 288u + (u32)(tap * 32 + s * 16) + lrow;
                        u32 bchunk = (u32)(nt2 * 2) + lsel;
                        ldsm_x4_t(bl[nt2], Bbase + krow * 128 + ((bchunk ^ (krow & 7)) << 4));
                    }
#pragma unroll
                    for (int mt = 0; mt < 2; mt++) {
                        u32 arow = (u32)((2 * r + 1 + mt) * 16) + lrow + rowoff;
                        u32 achunk = 4u + (u32)(s * 2) + lsel;
                        ldsm_x4(al[mt], Abase + arow * 128 + ((achunk ^ (arow & 7)) << 4));
                    }

                    // ---- 48 HMMA: p0 (Ah*Bh), p2 (Ah*Bl), p1 (Al*Bh) ----
#pragma unroll
                    for (int mt = 0; mt < 2; mt++)
#pragma unroll
                        for (int nt = 0; nt < 8; nt++)
                            mma_bf16(C[mt][nt], ah[mt], &bh[nt >> 1][(nt & 1) * 2]);
#pragma unroll
                    for (int mt = 0; mt < 2; mt++)
#pragma unroll
                        for (int nt = 0; nt < 8; nt++)
                            mma_bf16(C[mt][nt], ah[mt], &bl[nt >> 1][(nt & 1) * 2]);
#pragma unroll
                    for (int mt = 0; mt < 2; mt++)
#pragma unroll
                        for (int nt = 0; nt < 8; nt++)
                            mma_bf16(C[mt][nt], al[mt], &bh[nt >> 1][(nt & 1) * 2]);
                }
            }

            // ---- register epilogue: y-pool + x-pool via shuffles ----
            float* outb = g_h2 + (size_t)img * 3136;
#pragma unroll
            for (int nt = 0; nt < 8; nt++) {
                float p0 = fmaxf(C[0][nt][0], C[1][nt][0]);
                float p1 = fmaxf(C[0][nt][1], C[1][nt][1]);
                float p2 = fmaxf(C[0][nt][2], C[1][nt][2]);
                float p3 = fmaxf(C[0][nt][3], C[1][nt][3]);
                int srcl = (int)((lane + 4) & 31);
                float q0 = __shfl_sync(0xffffffffu, p0, srcl);
                float q1 = __shfl_sync(0xffffffffu, p1, srcl);
                float q2 = __shfl_sync(0xffffffffu, p2, srcl);
                float q3 = __shfl_sync(0xffffffffu, p3, srcl);
                float bx = s_bias[nt * 8 + 2 * kq];
                float by = s_bias[nt * 8 + 2 * kq + 1];

                if (g == 1 || g == 3 || g == 5) {
                    int pxo = (g - 1) >> 1;
                    float2 r0;
                    r0.x = fmaxf(fmaxf(p0, q0) + bx, 0.0f);
                    r0.y = fmaxf(fmaxf(p1, q1) + by, 0.0f);
                    *reinterpret_cast<float2*>(outb + (r * 7 + pxo) * 64 + nt * 8 + 2 * kq) = r0;
                    float2 r1;
                    r1.x = fmaxf(fmaxf(p2, q2) + bx, 0.0f);
                    r1.y = fmaxf(fmaxf(p3, q3) + by, 0.0f);
                    *reinterpret_cast<float2*>(outb + (r * 7 + pxo + 4) * 64 + nt * 8 + 2 * kq) = r1;
                } else if (g == 7) {
                    float2 r0;
                    r0.x = fmaxf(fmaxf(p0, q2) + bx, 0.0f);
                    r0.y = fmaxf(fmaxf(p1, q3) + by, 0.0f);
                    *reinterpret_cast<float2*>(outb + (r * 7 + 3) * 64 + nt * 8 + 2 * kq) = r0;
                }
            }
        }
        __syncthreads();
    }
}

// ---------------------------------------------------------------------------
// Kernel 3: FC  (N,3136) @ w'[3136,32] + bias -> (N,32)
// ---------------------------------------------------------------------------
#define FC_KT 112
#define FC_NB 16

__global__ __launch_bounds__(256)
void fc_kernel(const float* __restrict__ bias)
{
    __shared__ __align__(16) float a_s[FC_NB * FC_KT];
    __shared__ float b_s[FC_KT * 33];

    const int tid = threadIdx.x;
    const int n0  = blockIdx.x * FC_NB;
    const int d   = tid & 31;
    const int tr  = tid >> 5;

    float acc[2];
    float bv = bias[d];
    acc[0] = bv; acc[1] = bv;

    for (int kt = 0; kt < 3136; kt += FC_KT) {
        __syncthreads();
        for (int i = tid; i < FC_NB * FC_KT; i += 256) {
            int rr = i / FC_KT, c = i - rr * FC_KT;
            a_s[rr * FC_KT + c] = g_h2[(size_t)(n0 + rr) * 3136 + kt + c];
        }
        for (int i = tid; i < 32 * FC_KT; i += 256) {
            int c = i >> 5, dd = i & 31;
            b_s[c * 33 + dd] = g_fcw[(size_t)(kt + c) * 32 + dd];
        }
        __syncthreads();

#pragma unroll 4
        for (int kk = 0; kk < FC_KT; kk += 4) {
            float w0 = b_s[(kk + 0) * 33 + d];
            float w1 = b_s[(kk + 1) * 33 + d];
            float w2 = b_s[(kk + 2) * 33 + d];
            float w3 = b_s[(kk + 3) * 33 + d];
#pragma unroll
            for (int i = 0; i < 2; i++) {
                float4 av = *reinterpret_cast<const float4*>(
                    a_s + (tr * 2 + i) * FC_KT + kk);
                acc[i] = fmaf(av.x, w0, acc[i]);
                acc[i] = fmaf(av.y, w1, acc[i]);
                acc[i] = fmaf(av.z, w2, acc[i]);
                acc[i] = fmaf(av.w, w3, acc[i]);
            }
        }
    }

#pragma unroll
    for (int i = 0; i < 2; i++)
        g_fc[(size_t)(n0 + tr * 2 + i) * 32 + d] = acc[i];
}

// ---------------------------------------------------------------------------
// Kernel 4: hyperbolic MLR  (N,32) -> (N,10), c = 1
// ---------------------------------------------------------------------------
__global__ __launch_bounds__(256)
void mlr_kernel(const float* __restrict__ hw,
                const float* __restrict__ hb,
                float* __restrict__ out, int total)
{
    int i = blockIdx.x * blockDim.x + threadIdx.x;
    if (i >= total) return;
    int n = i / 10;
    int k = i - n * 10;

    const float* xv = g_fc + (size_t)n * 32;
    const float* wv = hw + k * 32;
    const float* bv = hb + k * 32;

    float x2 = 0.f, b2 = 0.f, w2 = 0.f, xb = 0.f, xw = 0.f, wb = 0.f;
#pragma unroll
    for (int j = 0; j < 32; j++) {
        float xj = xv[j], wj = wv[j], bj = bv[j];
        x2 += xj * xj;  b2 += bj * bj;  w2 += wj * wj;
        xb += xj * bj;  xw += xj * wj;  wb += wj * bj;
    }

    const float EPSf = 1e-5f;
    const float MN   = 0.99999f;

    float inner  = -xb;
    float w_norm = sqrtf(w2);
    float inv_wn = 1.0f / fmaxf(w_norm, 1e-12f);
    float wb_n   = -wb * inv_wn;
    float xw_n   = xw * inv_wn;

    float a_num = 1.0f + 2.0f * inner + x2;
    float b_num = 1.0f - b2;
    float denom = 1.0f + 2.0f * inner + x2 * b2;
    float alpha = a_num / fmaxf(denom, EPSf);
    float beta  = b_num / denom;
    float mob2  = alpha * alpha * b2 + 2.0f * alpha * beta * inner
                + beta * beta * x2;
    float sq    = sqrtf(mob2);
    float normalizer = (sq > MN) ? (MN / fmaxf(sq, EPSf)) : 1.0f;
    float mob2f = (sq < MN) ? mob2 : (MN * MN);
    float hyp   = (alpha * wb_n + beta * xw_n) * normalizer;
    float asin_in = 2.0f * hyp / fmaxf(1.0f - mob2f, EPSf);

    out[i] = (2.0f / fmaxf(1.0f - b2, EPSf)) * w_norm * asinhf(asin_in);
}

// ---------------------------------------------------------------------------
// Launch
// ---------------------------------------------------------------------------
extern "C" void kernel_launch(void* const* d_in, const int* in_sizes, int n_in,
                              void* d_out, int out_size) {
    const float* x   = (const float*)d_in[0];
    const float* w1  = (const float*)d_in[1];
    const float* b1  = (const float*)d_in[2];
    const float* w2  = (const float*)d_in[3];
    const float* b2  = (const float*)d_in[4];
    const float* fw  = (const float*)d_in[5];
    const float* fb  = (const float*)d_in[6];
    const float* hw  = (const float*)d_in[7];
    const float* hb  = (const float*)d_in[8];
    float* out = (float*)d_out;

    const int N = in_sizes[0] / 784;

    cudaFuncSetAttribute(conv2_mma_kernel,
                         cudaFuncAttributeMaxDynamicSharedMemorySize,
                         C2_SMEM_BYTES);

    prep_w2<<<9, 512>>>(w2);
    prep_fcw<<<98, 1024>>>(fw);
    conv1_kernel<<<N, 256>>>(x, w1, b1);
    int g2 = N < 296 ? N : 296;
    conv2_mma_kernel<<<g2, 256, C2_SMEM_BYTES>>>(b2, N);
    fc_kernel<<<N / FC_NB, 256>>>(fb);
    int total = N * 10;
    mlr_kernel<<<(total + 255) / 256, 256>>>(hw, hb, out, total);
}